// round 2
// baseline (speedup 1.0000x reference)
#include <cuda_runtime.h>
#include <cstdint>
#include <cstddef>

#define N_   50000
#define K_   48
#define C_   128
#define H_   8
#define D_   16
#define FF_  256
#define OUT_ 128
#define MT   32
#define NBLK ((N_ + MT - 1) / MT)

// ---------------- device scratch (allocation-free) ----------------
__device__ float g_QK[(size_t)N_ * H_ * C_];    // qk[n,h,c] = sum_d q[n,h,d]*wk[h*D+d,c]
__device__ float g_QB[(size_t)N_ * H_];         // q[n,h,:] . bk[h,:]
__device__ float g_CTXF[(size_t)N_ * H_ * C_];  // attn-weighted key features
__device__ float g_wqT[C_ * C_];
__device__ float g_wvT[C_ * C_];
__device__ float g_opT[C_ * C_];
__device__ float g_ff1T[C_ * FF_];
__device__ float g_ff2T[FF_ * C_];
__device__ float g_outT[C_ * OUT_];
__device__ int   g_mask_is_byte;

// ---------------- mask dtype detection ----------------
// If key_mask is stored as 1-byte bools, the int32 view of the first 16KB
// contains words > 1 with overwhelming probability (~20% true rate).
__global__ void kDetect(const int* __restrict__ km) {
    __shared__ int s;
    int t = threadIdx.x;
    if (t == 0) s = 0;
    __syncthreads();
    int bad = 0;
    for (int i = t; i < 4096; i += 256)
        if (((unsigned)km[i]) > 1u) bad = 1;
    if (bad) atomicOr(&s, 1);
    __syncthreads();
    if (t == 0) g_mask_is_byte = s;
}

// ---------------- weight transposes ----------------
__global__ void kPrep(const float* __restrict__ ipw, const float* __restrict__ opw,
                      const float* __restrict__ f1w, const float* __restrict__ f2w,
                      const float* __restrict__ ow) {
    int i = blockIdx.x * blockDim.x + threadIdx.x;
    if (i < 16384) {                       // wq
        int e = i >> 7, c = i & 127;
        g_wqT[c * C_ + e] = ipw[e * C_ + c];
    } else if (i < 32768) {                // wv
        int j = i - 16384; int e = j >> 7, c = j & 127;
        g_wvT[c * C_ + e] = ipw[(2 * C_ + e) * C_ + c];
    } else if (i < 49152) {                // out_proj_w
        int j = i - 32768; int e = j >> 7, c = j & 127;
        g_opT[c * C_ + e] = opw[e * C_ + c];
    } else if (i < 81920) {                // ff1_w (FF x C)
        int j = i - 49152; int f = j >> 7, c = j & 127;
        g_ff1T[c * FF_ + f] = f1w[f * C_ + c];
    } else if (i < 114688) {               // ff2_w (C x FF)
        int j = i - 81920; int e = j >> 8, f = j & 255;
        g_ff2T[f * C_ + e] = f2w[e * FF_ + f];
    } else if (i < 131072) {               // out_w (OUT x C)
        int j = i - 114688; int o = j >> 7, c = j & 127;
        g_outT[c * OUT_ + o] = ow[o * C_ + c];
    }
}

// ---------------- kernel A: Q = vf@wqT+bq ; qk[h,c] ; qb[h] ----------------
__global__ void __launch_bounds__(128) kA(const float* __restrict__ vf,
                                          const float* __restrict__ ipw,
                                          const float* __restrict__ ipb) {
    __shared__ float vsT[C_ * 33];
    __shared__ float QsT[C_ * 33];
    int t = threadIdx.x;
    int n0 = blockIdx.x * MT;

    #pragma unroll
    for (int m = 0; m < MT; m++) {
        int n = n0 + m; if (n >= N_) n = N_ - 1;
        vsT[t * 33 + m] = vf[(size_t)n * C_ + t];
    }
    __syncthreads();

    float acc[MT];
    #pragma unroll
    for (int m = 0; m < MT; m++) acc[m] = 0.f;
    for (int c = 0; c < C_; c++) {
        float w = g_wqT[c * C_ + t];
        #pragma unroll
        for (int m = 0; m < MT; m++) acc[m] = fmaf(vsT[c * 33 + m], w, acc[m]);
    }
    float bq = ipb[t];
    #pragma unroll
    for (int m = 0; m < MT; m++) QsT[t * 33 + m] = acc[m] + bq;
    __syncthreads();

    for (int h = 0; h < H_; h++) {
        #pragma unroll
        for (int m = 0; m < MT; m++) acc[m] = 0.f;
        #pragma unroll
        for (int d = 0; d < D_; d++) {
            int e = h * D_ + d;
            float w = ipw[(size_t)(C_ + e) * C_ + t];   // wk row e
            #pragma unroll
            for (int m = 0; m < MT; m++) acc[m] = fmaf(QsT[e * 33 + m], w, acc[m]);
        }
        #pragma unroll
        for (int m = 0; m < MT; m++) {
            int n = n0 + m;
            if (n < N_) g_QK[(size_t)n * (H_ * C_) + h * C_ + t] = acc[m];
        }
    }
    if (t < MT) {
        int n = n0 + t;
        if (n < N_) {
            for (int h = 0; h < H_; h++) {
                float s = 0.f;
                for (int d = 0; d < D_; d++) {
                    int e = h * D_ + d;
                    s = fmaf(QsT[e * 33 + t], ipb[C_ + e], s);
                }
                g_QB[(size_t)n * H_ + h] = s;
            }
        }
    }
}

// ---------------- kernel B: gather + pos_emb + scores + softmax + ctxfeat ----------------
__global__ void __launch_bounds__(128) kB(const float* __restrict__ vf,
                                          const float* __restrict__ coords,
                                          const int* __restrict__ kidx,
                                          const void* __restrict__ kmask,
                                          const float* __restrict__ kpw,
                                          const float* __restrict__ kpb) {
    __shared__ float kf[K_ * 133];
    __shared__ float qks[H_ * 132];
    __shared__ float sc[H_ * 52];
    __shared__ int   idxs[K_];
    __shared__ float relx[K_], rely[K_], relz[K_];
    __shared__ float qb_s[H_];
    __shared__ unsigned char msk[K_];

    int t = threadIdx.x;
    int n = blockIdx.x;
    int isbyte = g_mask_is_byte;

    if (t < K_) {
        int i = kidx[(size_t)n * K_ + t];
        idxs[t] = i;
        unsigned char mk;
        if (isbyte) mk = (((const unsigned char*)kmask)[(size_t)n * K_ + t] != 0);
        else        mk = (((const int*)kmask)[(size_t)n * K_ + t] != 0);
        msk[t] = mk;
        relx[t] = coords[(size_t)i * 3 + 0] - coords[(size_t)n * 3 + 0];
        rely[t] = coords[(size_t)i * 3 + 1] - coords[(size_t)n * 3 + 1];
        relz[t] = coords[(size_t)i * 3 + 2] - coords[(size_t)n * 3 + 2];
    }
    if (t < H_) qb_s[t] = g_QB[(size_t)n * H_ + t];
    #pragma unroll
    for (int h = 0; h < H_; h++)
        qks[h * 132 + t] = g_QK[(size_t)n * (H_ * C_) + h * C_ + t];

    float w0 = kpw[t * 3 + 0], w1 = kpw[t * 3 + 1], w2 = kpw[t * 3 + 2], pb = kpb[t];
    __syncthreads();

    for (int k = 0; k < K_; k++) {
        float pe = fmaf(relz[k], w2, fmaf(rely[k], w1, fmaf(relx[k], w0, pb)));
        pe = fmaxf(pe, 0.f);
        kf[k * 133 + t] = vf[(size_t)idxs[k] * C_ + t] + pe;
    }
    __syncthreads();

    // 384 scores over 128 threads (3 each)
    #pragma unroll
    for (int j = 0; j < 3; j++) {
        int s = t * 3 + j;
        int h = s / K_;
        int k = s - h * K_;
        float dot = 0.f;
        #pragma unroll 8
        for (int c = 0; c < C_; c++) dot = fmaf(kf[k * 133 + c], qks[h * 132 + c], dot);
        float val = (dot + qb_s[h]) * 0.25f;   // 1/sqrt(D)
        if (msk[k]) val = -1e9f;
        sc[h * 52 + k] = val;
    }
    __syncthreads();

    // softmax: warp w handles heads 2w, 2w+1
    {
        int w = t >> 5, l = t & 31;
        for (int hh = 0; hh < 2; hh++) {
            int h = 2 * w + hh;
            float a = sc[h * 52 + l];
            float b = (l < 16) ? sc[h * 52 + 32 + l] : -3.4e38f;
            float mx = fmaxf(a, b);
            #pragma unroll
            for (int o = 16; o > 0; o >>= 1) mx = fmaxf(mx, __shfl_xor_sync(0xffffffffu, mx, o));
            float ea = __expf(a - mx);
            float eb = (l < 16) ? __expf(b - mx) : 0.f;
            float sm = ea + eb;
            #pragma unroll
            for (int o = 16; o > 0; o >>= 1) sm += __shfl_xor_sync(0xffffffffu, sm, o);
            float inv = 1.f / sm;
            sc[h * 52 + l] = ea * inv;
            if (l < 16) sc[h * 52 + 32 + l] = eb * inv;
        }
    }
    __syncthreads();

    #pragma unroll
    for (int h = 0; h < H_; h++) {
        float acc = 0.f;
        #pragma unroll
        for (int k = 0; k < K_; k++) acc = fmaf(sc[h * 52 + k], kf[k * 133 + t], acc);
        g_CTXF[(size_t)n * (H_ * C_) + h * C_ + t] = acc;
    }
}

// ---------------- kernel C: ctx -> attend -> LN1 -> FF -> LN2 -> out -> LN3 -> relu ----------------
__global__ void __launch_bounds__(128) kC(const float* __restrict__ vf,
                                          const float* __restrict__ ipb,
                                          const float* __restrict__ opb,
                                          const float* __restrict__ ln1g, const float* __restrict__ ln1b,
                                          const float* __restrict__ ln2g, const float* __restrict__ ln2b,
                                          const float* __restrict__ ff1b, const float* __restrict__ ff2b,
                                          const float* __restrict__ outb,
                                          const float* __restrict__ ln3g, const float* __restrict__ ln3b,
                                          float* __restrict__ out) {
    __shared__ float bufA[C_ * 33];    // x vectors, transposed [channel][voxel]
    __shared__ float bufC[C_ * 33];    // staging: ctxfeat chunks / ctx / ff hidden / out-pre
    __shared__ float mean_s[MT], rstd_s[MT];

    int t = threadIdx.x;
    int n0 = blockIdx.x * MT;
    int h = t >> 4;                     // head owning output channel t

    float acc[MT], acc2[MT];
    #pragma unroll
    for (int m = 0; m < MT; m++) acc[m] = 0.f;

    // --- ctx[e=t] = sum_c wv[e,c]*ctxfeat[h(e),c], staged in 16-col chunks ---
    for (int ch = 0; ch < 8; ch++) {
        int c0 = ch * 16;
        __syncthreads();
        {
            int hh = t >> 4, cl = t & 15;   // 128 rows: (head, col-in-chunk)
            #pragma unroll
            for (int m = 0; m < MT; m++) {
                int n = n0 + m; if (n >= N_) n = N_ - 1;
                bufC[t * 33 + m] = g_CTXF[(size_t)n * (H_ * C_) + hh * C_ + c0 + cl];
            }
        }
        __syncthreads();
        #pragma unroll
        for (int cl = 0; cl < 16; cl++) {
            int c = c0 + cl;
            float w = g_wvT[c * C_ + t];
            int row = h * 16 + cl;
            #pragma unroll
            for (int m = 0; m < MT; m++) acc[m] = fmaf(bufC[row * 33 + m], w, acc[m]);
        }
    }
    float bv = ipb[2 * C_ + t];
    __syncthreads();
    #pragma unroll
    for (int m = 0; m < MT; m++) bufC[t * 33 + m] = acc[m] + bv;   // ctx
    __syncthreads();

    // --- attend = ctx @ opT + opb ; x1 = LN1(vf + attend) ---
    #pragma unroll
    for (int m = 0; m < MT; m++) acc2[m] = 0.f;
    for (int c = 0; c < C_; c++) {
        float w = g_opT[c * C_ + t];
        #pragma unroll
        for (int m = 0; m < MT; m++) acc2[m] = fmaf(bufC[c * 33 + m], w, acc2[m]);
    }
    {
        float ob = opb[t];
        #pragma unroll
        for (int m = 0; m < MT; m++) {
            int n = n0 + m; if (n >= N_) n = N_ - 1;
            bufA[t * 33 + m] = vf[(size_t)n * C_ + t] + acc2[m] + ob;
        }
    }
    __syncthreads();
    if (t < MT) {
        float s = 0.f, s2 = 0.f;
        for (int c = 0; c < C_; c++) { float v = bufA[c * 33 + t]; s += v; s2 = fmaf(v, v, s2); }
        float mn = s * (1.f / C_);
        mean_s[t] = mn; rstd_s[t] = rsqrtf(s2 * (1.f / C_) - mn * mn + 1e-5f);
    }
    __syncthreads();
    {
        float g = ln1g[t], b = ln1b[t];
        #pragma unroll
        for (int m = 0; m < MT; m++)
            bufA[t * 33 + m] = (bufA[t * 33 + m] - mean_s[m]) * rstd_s[m] * g + b;
    }
    __syncthreads();

    // --- FF: hidden in 2 chunks of 128, accumulate ff2 into acc2 ---
    #pragma unroll
    for (int m = 0; m < MT; m++) acc2[m] = 0.f;
    for (int fc = 0; fc < 2; fc++) {
        int f = fc * 128 + t;
        #pragma unroll
        for (int m = 0; m < MT; m++) acc[m] = 0.f;
        for (int c = 0; c < C_; c++) {
            float w = g_ff1T[c * FF_ + f];
            #pragma unroll
            for (int m = 0; m < MT; m++) acc[m] = fmaf(bufA[c * 33 + m], w, acc[m]);
        }
        float fb = ff1b[f];
        __syncthreads();
        #pragma unroll
        for (int m = 0; m < MT; m++) bufC[t * 33 + m] = fmaxf(acc[m] + fb, 0.f);
        __syncthreads();
        for (int fl = 0; fl < 128; fl++) {
            float w = g_ff2T[(size_t)(fc * 128 + fl) * C_ + t];
            #pragma unroll
            for (int m = 0; m < MT; m++) acc2[m] = fmaf(bufC[fl * 33 + m], w, acc2[m]);
        }
    }
    // --- x2 = LN2(x1 + ff) ---
    {
        float fb2 = ff2b[t];
        __syncthreads();
        #pragma unroll
        for (int m = 0; m < MT; m++)
            bufA[t * 33 + m] = bufA[t * 33 + m] + acc2[m] + fb2;
    }
    __syncthreads();
    if (t < MT) {
        float s = 0.f, s2 = 0.f;
        for (int c = 0; c < C_; c++) { float v = bufA[c * 33 + t]; s += v; s2 = fmaf(v, v, s2); }
        float mn = s * (1.f / C_);
        mean_s[t] = mn; rstd_s[t] = rsqrtf(s2 * (1.f / C_) - mn * mn + 1e-5f);
    }
    __syncthreads();
    {
        float g = ln2g[t], b = ln2b[t];
        #pragma unroll
        for (int m = 0; m < MT; m++)
            bufA[t * 33 + m] = (bufA[t * 33 + m] - mean_s[m]) * rstd_s[m] * g + b;
    }
    __syncthreads();

    // --- out_pre = x2 @ outT + out_b ; out = relu(LN3(out_pre)) ---
    #pragma unroll
    for (int m = 0; m < MT; m++) acc[m] = 0.f;
    for (int c = 0; c < C_; c++) {
        float w = g_outT[c * OUT_ + t];
        #pragma unroll
        for (int m = 0; m < MT; m++) acc[m] = fmaf(bufA[c * 33 + m], w, acc[m]);
    }
    {
        float ob = outb[t];
        #pragma unroll
        for (int m = 0; m < MT; m++) bufC[t * 33 + m] = acc[m] + ob;
    }
    __syncthreads();
    if (t < MT) {
        float s = 0.f, s2 = 0.f;
        for (int c = 0; c < OUT_; c++) { float v = bufC[c * 33 + t]; s += v; s2 = fmaf(v, v, s2); }
        float mn = s * (1.f / OUT_);
        mean_s[t] = mn; rstd_s[t] = rsqrtf(s2 * (1.f / OUT_) - mn * mn + 1e-5f);
    }
    __syncthreads();
    {
        float g = ln3g[t], b = ln3b[t];
        #pragma unroll
        for (int m = 0; m < MT; m++) {
            int n = n0 + m;
            if (n < N_) {
                float v = (bufC[t * 33 + m] - mean_s[m]) * rstd_s[m] * g + b;
                out[(size_t)n * OUT_ + t] = fmaxf(v, 0.f);
            }
        }
    }
}

// ---------------- launch ----------------
extern "C" void kernel_launch(void* const* d_in, const int* in_sizes, int n_in,
                              void* d_out, int out_size) {
    const float* vf     = (const float*)d_in[0];
    const float* coords = (const float*)d_in[1];
    const int*   kidx   = (const int*)  d_in[2];
    const void*  kmask  =               d_in[3];
    const float* ipw    = (const float*)d_in[4];
    const float* ipb    = (const float*)d_in[5];
    const float* opw    = (const float*)d_in[6];
    const float* opb    = (const float*)d_in[7];
    const float* kpw    = (const float*)d_in[8];
    const float* kpb    = (const float*)d_in[9];
    const float* ln1g   = (const float*)d_in[10];
    const float* ln1b   = (const float*)d_in[11];
    const float* ln2g   = (const float*)d_in[12];
    const float* ln2b   = (const float*)d_in[13];
    const float* ff1w   = (const float*)d_in[14];
    const float* ff1b   = (const float*)d_in[15];
    const float* ff2w   = (const float*)d_in[16];
    const float* ff2b   = (const float*)d_in[17];
    const float* outw   = (const float*)d_in[18];
    const float* outb   = (const float*)d_in[19];
    const float* ln3g   = (const float*)d_in[20];
    const float* ln3b   = (const float*)d_in[21];

    kDetect<<<1, 256>>>((const int*)kmask);
    kPrep<<<(131072 + 255) / 256, 256>>>(ipw, opw, ff1w, ff2w, outw);
    kA<<<NBLK, 128>>>(vf, ipw, ipb);
    kB<<<N_, 128>>>(vf, coords, kidx, kmask, kpw, kpb);
    kC<<<NBLK, 128>>>(vf, ipb, opb, ln1g, ln1b, ln2g, ln2b,
                      ff1b, ff2b, outb, ln3g, ln3b, (float*)d_out);
}

// round 3
// speedup vs baseline: 1.7050x; 1.7050x over previous
#include <cuda_runtime.h>
#include <cstdint>
#include <cstddef>

#define N_   50000
#define K_   48
#define C_   128
#define H_   8
#define D_   16
#define FF_  256
#define OUT_ 128
#define MT   32
#define S_   36     // row stride (floats) for m-buffers: 16B-aligned, f4-stride 9 (odd)
#define NBLK ((N_ + MT - 1) / MT)

// ---------------- device scratch (allocation-free) ----------------
__device__ float g_QK[(size_t)N_ * H_ * C_];
__device__ float g_QB[(size_t)N_ * H_];
__device__ float g_CTXF[(size_t)N_ * H_ * C_];
__device__ float g_wqT[C_ * C_];
__device__ float g_wvT[C_ * C_];
__device__ float g_opT[C_ * C_];
__device__ float g_ff1T[C_ * FF_];
__device__ float g_ff2T[FF_ * C_];
__device__ float g_outT[C_ * OUT_];
__device__ int   g_mask_is_byte;

// ---------------- mask dtype detection ----------------
__global__ void kDetect(const int* __restrict__ km) {
    __shared__ int s;
    int t = threadIdx.x;
    if (t == 0) s = 0;
    __syncthreads();
    int bad = 0;
    for (int i = t; i < 4096; i += 256)
        if (((unsigned)km[i]) > 1u) bad = 1;
    if (bad) atomicOr(&s, 1);
    __syncthreads();
    if (t == 0) g_mask_is_byte = s;
}

// ---------------- weight transposes ----------------
__global__ void kPrep(const float* __restrict__ ipw, const float* __restrict__ opw,
                      const float* __restrict__ f1w, const float* __restrict__ f2w,
                      const float* __restrict__ ow) {
    int i = blockIdx.x * blockDim.x + threadIdx.x;
    if (i < 16384) {
        int e = i >> 7, c = i & 127;
        g_wqT[c * C_ + e] = ipw[e * C_ + c];
    } else if (i < 32768) {
        int j = i - 16384; int e = j >> 7, c = j & 127;
        g_wvT[c * C_ + e] = ipw[(2 * C_ + e) * C_ + c];
    } else if (i < 49152) {
        int j = i - 32768; int e = j >> 7, c = j & 127;
        g_opT[c * C_ + e] = opw[e * C_ + c];
    } else if (i < 81920) {
        int j = i - 49152; int f = j >> 7, c = j & 127;
        g_ff1T[c * FF_ + f] = f1w[f * C_ + c];
    } else if (i < 114688) {
        int j = i - 81920; int e = j >> 8, f = j & 255;
        g_ff2T[f * C_ + e] = f2w[e * FF_ + f];
    } else if (i < 131072) {
        int j = i - 114688; int o = j >> 7, c = j & 127;
        g_outT[c * OUT_ + o] = ow[o * C_ + c];
    }
}

// ---------------- kernel A ----------------
__global__ void __launch_bounds__(128) kA(const float* __restrict__ vf,
                                          const float* __restrict__ ipw,
                                          const float* __restrict__ ipb) {
    __shared__ float vsT[C_ * S_];
    __shared__ float QsT[C_ * S_];
    int t = threadIdx.x;
    int n0 = blockIdx.x * MT;

    float r[MT];
    #pragma unroll
    for (int m = 0; m < MT; m++) {
        int n = n0 + m; if (n >= N_) n = N_ - 1;
        r[m] = vf[(size_t)n * C_ + t];
    }
    #pragma unroll
    for (int m4 = 0; m4 < 8; m4++)
        *(float4*)&vsT[t * S_ + 4 * m4] = make_float4(r[4*m4], r[4*m4+1], r[4*m4+2], r[4*m4+3]);
    __syncthreads();

    float acc[MT];
    #pragma unroll
    for (int m = 0; m < MT; m++) acc[m] = 0.f;
    for (int c = 0; c < C_; c++) {
        float w = g_wqT[c * C_ + t];
        #pragma unroll
        for (int m4 = 0; m4 < 8; m4++) {
            float4 v = *(const float4*)&vsT[c * S_ + 4 * m4];
            acc[4*m4+0] = fmaf(v.x, w, acc[4*m4+0]);
            acc[4*m4+1] = fmaf(v.y, w, acc[4*m4+1]);
            acc[4*m4+2] = fmaf(v.z, w, acc[4*m4+2]);
            acc[4*m4+3] = fmaf(v.w, w, acc[4*m4+3]);
        }
    }
    float bq = ipb[t];
    #pragma unroll
    for (int m4 = 0; m4 < 8; m4++)
        *(float4*)&QsT[t * S_ + 4 * m4] = make_float4(acc[4*m4]+bq, acc[4*m4+1]+bq,
                                                      acc[4*m4+2]+bq, acc[4*m4+3]+bq);
    __syncthreads();

    for (int h = 0; h < H_; h++) {
        #pragma unroll
        for (int m = 0; m < MT; m++) acc[m] = 0.f;
        #pragma unroll
        for (int d = 0; d < D_; d++) {
            int e = h * D_ + d;
            float w = ipw[(size_t)(C_ + e) * C_ + t];
            #pragma unroll
            for (int m4 = 0; m4 < 8; m4++) {
                float4 v = *(const float4*)&QsT[e * S_ + 4 * m4];
                acc[4*m4+0] = fmaf(v.x, w, acc[4*m4+0]);
                acc[4*m4+1] = fmaf(v.y, w, acc[4*m4+1]);
                acc[4*m4+2] = fmaf(v.z, w, acc[4*m4+2]);
                acc[4*m4+3] = fmaf(v.w, w, acc[4*m4+3]);
            }
        }
        #pragma unroll
        for (int m = 0; m < MT; m++) {
            int n = n0 + m;
            if (n < N_) g_QK[(size_t)n * (H_ * C_) + h * C_ + t] = acc[m];
        }
    }
    if (t < MT) {
        int n = n0 + t;
        if (n < N_) {
            for (int h = 0; h < H_; h++) {
                float s = 0.f;
                for (int d = 0; d < D_; d++) {
                    int e = h * D_ + d;
                    s = fmaf(QsT[e * S_ + t], ipb[C_ + e], s);
                }
                g_QB[(size_t)n * H_ + h] = s;
            }
        }
    }
}

// ---------------- kernel B ----------------
__global__ void __launch_bounds__(128) kB(const float* __restrict__ vf,
                                          const float* __restrict__ coords,
                                          const int* __restrict__ kidx,
                                          const void* __restrict__ kmask,
                                          const float* __restrict__ kpw,
                                          const float* __restrict__ kpb) {
    __shared__ float4 kf4[K_ * 33];
    __shared__ float4 qk4[H_ * 33];
    __shared__ __align__(16) float attnS[K_ * 8];   // [k*8 + h]
    __shared__ int   idxs[K_];
    __shared__ float relx[K_], rely[K_], relz[K_];
    __shared__ float qb_s[H_];
    __shared__ unsigned char msk[K_];

    int t = threadIdx.x;
    int n = blockIdx.x;
    int isbyte = g_mask_is_byte;

    if (t < K_) {
        int i = kidx[(size_t)n * K_ + t];
        idxs[t] = i;
        unsigned char mk;
        if (isbyte) mk = (((const unsigned char*)kmask)[(size_t)n * K_ + t] != 0);
        else        mk = (((const int*)kmask)[(size_t)n * K_ + t] != 0);
        msk[t] = mk;
        relx[t] = coords[(size_t)i * 3 + 0] - coords[(size_t)n * 3 + 0];
        rely[t] = coords[(size_t)i * 3 + 1] - coords[(size_t)n * 3 + 1];
        relz[t] = coords[(size_t)i * 3 + 2] - coords[(size_t)n * 3 + 2];
    }
    if (t < H_) qb_s[t] = g_QB[(size_t)n * H_ + t];
    {   // stage qk rows: thread -> (h = t>>4, float4-pair)
        int h = t >> 4, c2 = (t & 15) * 2;
        const float4* src = (const float4*)(g_QK + (size_t)n * (H_ * C_) + h * C_);
        qk4[h * 33 + c2]     = __ldg(src + c2);
        qk4[h * 33 + c2 + 1] = __ldg(src + c2 + 1);
    }

    int c4 = t & 31, q = t >> 5;
    float4 wa = __ldg((const float4*)(kpw + 12 * c4));
    float4 wb = __ldg((const float4*)(kpw + 12 * c4 + 4));
    float4 wc = __ldg((const float4*)(kpw + 12 * c4 + 8));
    float4 pb4 = __ldg((const float4*)(kpb + 4 * c4));
    __syncthreads();

    // gather + posemb: 4 channels x 12 keys per thread
    #pragma unroll
    for (int kk = 0; kk < 12; kk++) {
        int k = q * 12 + kk;
        int i = idxs[k];
        float4 v = __ldg((const float4*)(vf + (size_t)i * C_) + c4);
        float rx = relx[k], ry = rely[k], rz = relz[k];
        float p0 = fmaf(rz, wa.z, fmaf(ry, wa.y, fmaf(rx, wa.x, pb4.x)));
        float p1 = fmaf(rz, wb.y, fmaf(ry, wb.x, fmaf(rx, wa.w, pb4.y)));
        float p2 = fmaf(rz, wc.x, fmaf(ry, wb.w, fmaf(rx, wb.z, pb4.z)));
        float p3 = fmaf(rz, wc.w, fmaf(ry, wc.z, fmaf(rx, wc.y, pb4.w)));
        v.x += fmaxf(p0, 0.f); v.y += fmaxf(p1, 0.f);
        v.z += fmaxf(p2, 0.f); v.w += fmaxf(p3, 0.f);
        kf4[k * 33 + c4] = v;
    }
    __syncthreads();

    // scores: thread -> (k, 4-head group); kf float4 reused across 4 heads
    if (t < 96) {
        int k = t % 48, g = t / 48;
        float a0 = 0.f, a1 = 0.f, a2 = 0.f, a3 = 0.f;
        #pragma unroll 8
        for (int c = 0; c < 32; c++) {
            float4 f  = kf4[k * 33 + c];
            float4 q0 = qk4[(4*g+0) * 33 + c];
            float4 q1 = qk4[(4*g+1) * 33 + c];
            float4 q2 = qk4[(4*g+2) * 33 + c];
            float4 q3 = qk4[(4*g+3) * 33 + c];
            a0 = fmaf(f.w, q0.w, fmaf(f.z, q0.z, fmaf(f.y, q0.y, fmaf(f.x, q0.x, a0))));
            a1 = fmaf(f.w, q1.w, fmaf(f.z, q1.z, fmaf(f.y, q1.y, fmaf(f.x, q1.x, a1))));
            a2 = fmaf(f.w, q2.w, fmaf(f.z, q2.z, fmaf(f.y, q2.y, fmaf(f.x, q2.x, a2))));
            a3 = fmaf(f.w, q3.w, fmaf(f.z, q3.z, fmaf(f.y, q3.y, fmaf(f.x, q3.x, a3))));
        }
        bool mk = msk[k] != 0;
        attnS[k*8 + 4*g + 0] = mk ? -1e9f : (a0 + qb_s[4*g+0]) * 0.25f;
        attnS[k*8 + 4*g + 1] = mk ? -1e9f : (a1 + qb_s[4*g+1]) * 0.25f;
        attnS[k*8 + 4*g + 2] = mk ? -1e9f : (a2 + qb_s[4*g+2]) * 0.25f;
        attnS[k*8 + 4*g + 3] = mk ? -1e9f : (a3 + qb_s[4*g+3]) * 0.25f;
    }
    __syncthreads();

    // softmax: warp w -> heads 2w, 2w+1
    {
        int w = t >> 5, l = t & 31;
        #pragma unroll
        for (int hh = 0; hh < 2; hh++) {
            int h = 2 * w + hh;
            float a = attnS[l * 8 + h];
            float b = (l < 16) ? attnS[(32 + l) * 8 + h] : -3.4e38f;
            float mx = fmaxf(a, b);
            #pragma unroll
            for (int o = 16; o > 0; o >>= 1) mx = fmaxf(mx, __shfl_xor_sync(0xffffffffu, mx, o));
            float ea = __expf(a - mx);
            float eb = (l < 16) ? __expf(b - mx) : 0.f;
            float sm = ea + eb;
            #pragma unroll
            for (int o = 16; o > 0; o >>= 1) sm += __shfl_xor_sync(0xffffffffu, sm, o);
            float inv = 1.f / sm;
            attnS[l * 8 + h] = ea * inv;
            if (l < 16) attnS[(32 + l) * 8 + h] = eb * inv;
        }
    }
    __syncthreads();

    // ctxfeat: thread -> (4-head group g, c4); kf float4 reused across 4 heads
    if (t < 64) {
        int g = t >> 5, cc = t & 31;
        float4 A0 = make_float4(0,0,0,0), A1 = A0, A2 = A0, A3 = A0;
        #pragma unroll 8
        for (int k = 0; k < K_; k++) {
            float4 f = kf4[k * 33 + cc];
            float4 a = *(const float4*)&attnS[k * 8 + 4 * g];
            A0.x = fmaf(a.x, f.x, A0.x); A0.y = fmaf(a.x, f.y, A0.y);
            A0.z = fmaf(a.x, f.z, A0.z); A0.w = fmaf(a.x, f.w, A0.w);
            A1.x = fmaf(a.y, f.x, A1.x); A1.y = fmaf(a.y, f.y, A1.y);
            A1.z = fmaf(a.y, f.z, A1.z); A1.w = fmaf(a.y, f.w, A1.w);
            A2.x = fmaf(a.z, f.x, A2.x); A2.y = fmaf(a.z, f.y, A2.y);
            A2.z = fmaf(a.z, f.z, A2.z); A2.w = fmaf(a.z, f.w, A2.w);
            A3.x = fmaf(a.w, f.x, A3.x); A3.y = fmaf(a.w, f.y, A3.y);
            A3.z = fmaf(a.w, f.z, A3.z); A3.w = fmaf(a.w, f.w, A3.w);
        }
        float4* dst = (float4*)(g_CTXF + (size_t)n * (H_ * C_));
        dst[(4*g+0) * 32 + cc] = A0;
        dst[(4*g+1) * 32 + cc] = A1;
        dst[(4*g+2) * 32 + cc] = A2;
        dst[(4*g+3) * 32 + cc] = A3;
    }
}

// ---------------- kernel C ----------------
#define GEMM_STEP(BUF, ROW, W) do {                                        \
    float w_ = (W);                                                        \
    _Pragma("unroll")                                                      \
    for (int m4 = 0; m4 < 8; m4++) {                                       \
        float4 v_ = *(const float4*)&(BUF)[(ROW) * S_ + 4 * m4];           \
        acc[4*m4+0] = fmaf(v_.x, w_, acc[4*m4+0]);                         \
        acc[4*m4+1] = fmaf(v_.y, w_, acc[4*m4+1]);                         \
        acc[4*m4+2] = fmaf(v_.z, w_, acc[4*m4+2]);                         \
        acc[4*m4+3] = fmaf(v_.w, w_, acc[4*m4+3]);                         \
    } } while (0)

__global__ void __launch_bounds__(128) kC(const float* __restrict__ vf,
                                          const float* __restrict__ ipb,
                                          const float* __restrict__ opb,
                                          const float* __restrict__ ln1g, const float* __restrict__ ln1b,
                                          const float* __restrict__ ln2g, const float* __restrict__ ln2b,
                                          const float* __restrict__ ff1b, const float* __restrict__ ff2b,
                                          const float* __restrict__ outb,
                                          const float* __restrict__ ln3g, const float* __restrict__ ln3b,
                                          float* __restrict__ out) {
    __shared__ float bufA[C_ * S_];
    __shared__ float bufC[C_ * S_];
    __shared__ float mean_s[MT], rstd_s[MT];

    int t = threadIdx.x;
    int n0 = blockIdx.x * MT;
    int h = t >> 4;

    float acc[MT], keep[MT];
    #pragma unroll
    for (int m = 0; m < MT; m++) acc[m] = 0.f;

    // --- ctx: staged ctxfeat chunks (8 x 16 cols) ---
    for (int ch = 0; ch < 8; ch++) {
        int c0 = ch * 16;
        __syncthreads();
        {
            int hh = t >> 4, cl = t & 15;
            float r[MT];
            #pragma unroll
            for (int m = 0; m < MT; m++) {
                int n = n0 + m; if (n >= N_) n = N_ - 1;
                r[m] = g_CTXF[(size_t)n * (H_ * C_) + hh * C_ + c0 + cl];
            }
            #pragma unroll
            for (int m4 = 0; m4 < 8; m4++)
                *(float4*)&bufC[t * S_ + 4 * m4] =
                    make_float4(r[4*m4], r[4*m4+1], r[4*m4+2], r[4*m4+3]);
        }
        __syncthreads();
        #pragma unroll
        for (int cl = 0; cl < 16; cl++) {
            int c = c0 + cl;
            GEMM_STEP(bufC, h * 16 + cl, g_wvT[c * C_ + t]);
        }
    }
    float bv = ipb[2 * C_ + t];
    __syncthreads();
    #pragma unroll
    for (int m4 = 0; m4 < 8; m4++)
        *(float4*)&bufC[t * S_ + 4 * m4] = make_float4(acc[4*m4]+bv, acc[4*m4+1]+bv,
                                                       acc[4*m4+2]+bv, acc[4*m4+3]+bv);
    __syncthreads();

    // --- attend + residual -> LN1 ---
    #pragma unroll
    for (int m = 0; m < MT; m++) acc[m] = 0.f;
    for (int c = 0; c < C_; c++) GEMM_STEP(bufC, c, g_opT[c * C_ + t]);
    {
        float ob = opb[t];
        float r[MT];
        #pragma unroll
        for (int m = 0; m < MT; m++) {
            int n = n0 + m; if (n >= N_) n = N_ - 1;
            r[m] = vf[(size_t)n * C_ + t] + acc[m] + ob;
        }
        #pragma unroll
        for (int m4 = 0; m4 < 8; m4++)
            *(float4*)&bufA[t * S_ + 4 * m4] =
                make_float4(r[4*m4], r[4*m4+1], r[4*m4+2], r[4*m4+3]);
    }
    __syncthreads();
    if (t < MT) {
        float s = 0.f, s2 = 0.f;
        for (int c = 0; c < C_; c++) { float v = bufA[c * S_ + t]; s += v; s2 = fmaf(v, v, s2); }
        float mn = s * (1.f / C_);
        mean_s[t] = mn; rstd_s[t] = rsqrtf(s2 * (1.f / C_) - mn * mn + 1e-5f);
    }
    __syncthreads();
    {
        float g = ln1g[t], b = ln1b[t];
        #pragma unroll
        for (int m = 0; m < MT; m++) {
            float v = (bufA[t * S_ + m] - mean_s[m]) * rstd_s[m] * g + b;
            bufA[t * S_ + m] = v;
            keep[m] = v;
        }
    }
    __syncthreads();

    // --- FF ---
    float acc2[MT];
    #pragma unroll
    for (int m = 0; m < MT; m++) acc2[m] = 0.f;
    for (int fc = 0; fc < 2; fc++) {
        int f = fc * 128 + t;
        #pragma unroll
        for (int m = 0; m < MT; m++) acc[m] = 0.f;
        for (int c = 0; c < C_; c++) GEMM_STEP(bufA, c, g_ff1T[c * FF_ + f]);
        float fb = ff1b[f];
        __syncthreads();
        #pragma unroll
        for (int m4 = 0; m4 < 8; m4++)
            *(float4*)&bufC[t * S_ + 4 * m4] =
                make_float4(fmaxf(acc[4*m4]+fb, 0.f),  fmaxf(acc[4*m4+1]+fb, 0.f),
                            fmaxf(acc[4*m4+2]+fb, 0.f), fmaxf(acc[4*m4+3]+fb, 0.f));
        __syncthreads();
        {
            float* accp = acc2;
            float* acc = accp;   // reuse macro on acc2
            for (int fl = 0; fl < 128; fl++)
                GEMM_STEP(bufC, fl, g_ff2T[(size_t)(fc * 128 + fl) * C_ + t]);
        }
    }
    // --- LN2 ---
    {
        float fb2 = ff2b[t];
        __syncthreads();
        #pragma unroll
        for (int m4 = 0; m4 < 8; m4++)
            *(float4*)&bufA[t * S_ + 4 * m4] =
                make_float4(keep[4*m4]+acc2[4*m4]+fb2,   keep[4*m4+1]+acc2[4*m4+1]+fb2,
                            keep[4*m4+2]+acc2[4*m4+2]+fb2, keep[4*m4+3]+acc2[4*m4+3]+fb2);
    }
    __syncthreads();
    if (t < MT) {
        float s = 0.f, s2 = 0.f;
        for (int c = 0; c < C_; c++) { float v = bufA[c * S_ + t]; s += v; s2 = fmaf(v, v, s2); }
        float mn = s * (1.f / C_);
        mean_s[t] = mn; rstd_s[t] = rsqrtf(s2 * (1.f / C_) - mn * mn + 1e-5f);
    }
    __syncthreads();
    {
        float g = ln2g[t], b = ln2b[t];
        #pragma unroll
        for (int m = 0; m < MT; m++)
            bufA[t * S_ + m] = (bufA[t * S_ + m] - mean_s[m]) * rstd_s[m] * g + b;
    }
    __syncthreads();

    // --- out projection -> LN3 -> relu ---
    #pragma unroll
    for (int m = 0; m < MT; m++) acc[m] = 0.f;
    for (int c = 0; c < C_; c++) GEMM_STEP(bufA, c, g_outT[c * OUT_ + t]);
    {
        float ob = outb[t];
        #pragma unroll
        for (int m4 = 0; m4 < 8; m4++)
            *(float4*)&bufC[t * S_ + 4 * m4] = make_float4(acc[4*m4]+ob, acc[4*m4+1]+ob,
                                                           acc[4*m4+2]+ob, acc[4*m4+3]+ob);
    }
    __syncthreads();
    if (t < MT) {
        float s = 0.f, s2 = 0.f;
        for (int c = 0; c < OUT_; c++) { float v = bufC[c * S_ + t]; s += v; s2 = fmaf(v, v, s2); }
        float mn = s * (1.f / OUT_);
        mean_s[t] = mn; rstd_s[t] = rsqrtf(s2 * (1.f / OUT_) - mn * mn + 1e-5f);
    }
    __syncthreads();
    {
        float g = ln3g[t], b = ln3b[t];
        #pragma unroll
        for (int m = 0; m < MT; m++) {
            int n = n0 + m;
            if (n < N_) {
                float v = (bufC[t * S_ + m] - mean_s[m]) * rstd_s[m] * g + b;
                out[(size_t)n * OUT_ + t] = fmaxf(v, 0.f);
            }
        }
    }
}

// ---------------- launch ----------------
extern "C" void kernel_launch(void* const* d_in, const int* in_sizes, int n_in,
                              void* d_out, int out_size) {
    const float* vf     = (const float*)d_in[0];
    const float* coords = (const float*)d_in[1];
    const int*   kidx   = (const int*)  d_in[2];
    const void*  kmask  =               d_in[3];
    const float* ipw    = (const float*)d_in[4];
    const float* ipb    = (const float*)d_in[5];
    const float* opw    = (const float*)d_in[6];
    const float* opb    = (const float*)d_in[7];
    const float* kpw    = (const float*)d_in[8];
    const float* kpb    = (const float*)d_in[9];
    const float* ln1g   = (const float*)d_in[10];
    const float* ln1b   = (const float*)d_in[11];
    const float* ln2g   = (const float*)d_in[12];
    const float* ln2b   = (const float*)d_in[13];
    const float* ff1w   = (const float*)d_in[14];
    const float* ff1b   = (const float*)d_in[15];
    const float* ff2w   = (const float*)d_in[16];
    const float* ff2b   = (const float*)d_in[17];
    const float* outw   = (const float*)d_in[18];
    const float* outb   = (const float*)d_in[19];
    const float* ln3g   = (const float*)d_in[20];
    const float* ln3b   = (const float*)d_in[21];

    kDetect<<<1, 256>>>((const int*)kmask);
    kPrep<<<(131072 + 255) / 256, 256>>>(ipw, opw, ff1w, ff2w, outw);
    kA<<<NBLK, 128>>>(vf, ipw, ipb);
    kB<<<N_, 128>>>(vf, coords, kidx, kmask, kpw, kpb);
    kC<<<NBLK, 128>>>(vf, ipb, opb, ln1g, ln1b, ln2g, ln2b,
                      ff1b, ff2b, outb, ln3g, ln3b, (float*)d_out);
}

// round 5
// speedup vs baseline: 1.7539x; 1.0287x over previous
#include <cuda_runtime.h>
#include <cstdint>
#include <cstddef>

#define N_   50000
#define K_   48
#define C_   128
#define H_   8
#define D_   16
#define FF_  256
#define OUT_ 128
#define MT   32
#define S_   36
#define NBLK ((N_ + MT - 1) / MT)

typedef unsigned long long u64;

// ---- f32x2 packed helpers (Blackwell sm_100+) ----
__device__ __forceinline__ u64 pk2(float w) {
    u64 r; asm("mov.b64 %0,{%1,%1};" : "=l"(r) : "f"(w)); return r;
}
__device__ __forceinline__ void f2(u64& d, u64 a, u64 b) {
    asm("fma.rn.f32x2 %0,%1,%2,%0;" : "+l"(d) : "l"(a), "l"(b));
}
__device__ __forceinline__ float2 up2(u64 a) {
    float2 r; asm("mov.b64 {%0,%1},%2;" : "=f"(r.x), "=f"(r.y) : "l"(a)); return r;
}

// ---------------- device scratch ----------------
__device__ float g_QK[(size_t)N_ * H_ * C_];
__device__ float g_QB[(size_t)N_ * H_];
__device__ float g_CTXF[(size_t)N_ * H_ * C_];
__device__ float g_wqT[C_ * C_];
__device__ float g_wvT[C_ * C_];
__device__ float g_opT[C_ * C_];
__device__ float g_ff1T[C_ * FF_];
__device__ float g_ff2T[FF_ * C_];
__device__ float g_outT[C_ * OUT_];
__device__ int   g_mask_is_byte;

// ---------------- mask dtype detection ----------------
__global__ void kDetect(const int* __restrict__ km) {
    __shared__ int s;
    int t = threadIdx.x;
    if (t == 0) s = 0;
    __syncthreads();
    int bad = 0;
    for (int i = t; i < 4096; i += 256)
        if (((unsigned)km[i]) > 1u) bad = 1;
    if (bad) atomicOr(&s, 1);
    __syncthreads();
    if (t == 0) g_mask_is_byte = s;
}

// ---------------- weight transposes ----------------
__global__ void kPrep(const float* __restrict__ ipw, const float* __restrict__ opw,
                      const float* __restrict__ f1w, const float* __restrict__ f2w,
                      const float* __restrict__ ow) {
    int i = blockIdx.x * blockDim.x + threadIdx.x;
    if (i < 16384) {
        int e = i >> 7, c = i & 127;
        g_wqT[c * C_ + e] = ipw[e * C_ + c];
    } else if (i < 32768) {
        int j = i - 16384; int e = j >> 7, c = j & 127;
        g_wvT[c * C_ + e] = ipw[(2 * C_ + e) * C_ + c];
    } else if (i < 49152) {
        int j = i - 32768; int e = j >> 7, c = j & 127;
        g_opT[c * C_ + e] = opw[e * C_ + c];
    } else if (i < 81920) {
        int j = i - 49152; int f = j >> 7, c = j & 127;
        g_ff1T[c * FF_ + f] = f1w[f * C_ + c];
    } else if (i < 114688) {
        int j = i - 81920; int e = j >> 8, f = j & 255;
        g_ff2T[f * C_ + e] = f2w[e * FF_ + f];
    } else if (i < 131072) {
        int j = i - 114688; int o = j >> 7, c = j & 127;
        g_outT[c * OUT_ + o] = ow[o * C_ + c];
    }
}

// packed-GEMM step: ACC (u64[16]) += BUF[ROW, 0..31] * W
#define GSTEP(BUF, ROW, W, ACC) do {                                       \
    u64 w2_ = pk2(W);                                                      \
    _Pragma("unroll")                                                      \
    for (int p_ = 0; p_ < 8; p_++) {                                       \
        ulonglong2 v_ = *(const ulonglong2*)&(BUF)[(ROW) * S_ + 4 * p_];   \
        f2((ACC)[2 * p_],     v_.x, w2_);                                  \
        f2((ACC)[2 * p_ + 1], v_.y, w2_);                                  \
    } } while (0)

// unpack u64[16] accumulators into float[32]
#define UNPK(ACC, R) do {                                                  \
    _Pragma("unroll")                                                      \
    for (int p_ = 0; p_ < 16; p_++) {                                      \
        float2 s_ = up2((ACC)[p_]);                                        \
        (R)[2 * p_] = s_.x; (R)[2 * p_ + 1] = s_.y;                        \
    } } while (0)

// ---------------- kernel A ----------------
__global__ void __launch_bounds__(128) kA(const float* __restrict__ vf,
                                          const float* __restrict__ ipw,
                                          const float* __restrict__ ipb) {
    __shared__ float vsT[C_ * S_];
    __shared__ float QsT[C_ * S_];
    int t = threadIdx.x;
    int n0 = blockIdx.x * MT;

    float r[MT];
    #pragma unroll
    for (int m = 0; m < MT; m++) {
        int n = n0 + m; if (n >= N_) n = N_ - 1;
        r[m] = vf[(size_t)n * C_ + t];
    }
    #pragma unroll
    for (int m4 = 0; m4 < 8; m4++)
        *(float4*)&vsT[t * S_ + 4 * m4] = make_float4(r[4*m4], r[4*m4+1], r[4*m4+2], r[4*m4+3]);
    __syncthreads();

    u64 acc[16];
    #pragma unroll
    for (int p = 0; p < 16; p++) acc[p] = 0;
    for (int c = 0; c < C_; c++) GSTEP(vsT, c, g_wqT[c * C_ + t], acc);
    {
        float q[MT]; UNPK(acc, q);
        float bq = ipb[t];
        #pragma unroll
        for (int m4 = 0; m4 < 8; m4++)
            *(float4*)&QsT[t * S_ + 4 * m4] = make_float4(q[4*m4]+bq, q[4*m4+1]+bq,
                                                          q[4*m4+2]+bq, q[4*m4+3]+bq);
    }
    __syncthreads();

    for (int h = 0; h < H_; h++) {
        #pragma unroll
        for (int p = 0; p < 16; p++) acc[p] = 0;
        #pragma unroll
        for (int d = 0; d < D_; d++) {
            int e = h * D_ + d;
            GSTEP(QsT, e, ipw[(size_t)(C_ + e) * C_ + t], acc);
        }
        float q[MT]; UNPK(acc, q);
        #pragma unroll
        for (int m = 0; m < MT; m++) {
            int n = n0 + m;
            if (n < N_) g_QK[(size_t)n * (H_ * C_) + h * C_ + t] = q[m];
        }
    }
    if (t < MT) {
        int n = n0 + t;
        if (n < N_) {
            for (int h = 0; h < H_; h++) {
                float s = 0.f;
                for (int d = 0; d < D_; d++) {
                    int e = h * D_ + d;
                    s = fmaf(QsT[e * S_ + t], ipb[C_ + e], s);
                }
                g_QB[(size_t)n * H_ + h] = s;
            }
        }
    }
}

// ---------------- kernel B ----------------
__global__ void __launch_bounds__(128) kB(const float* __restrict__ vf,
                                          const float* __restrict__ coords,
                                          const int* __restrict__ kidx,
                                          const void* __restrict__ kmask,
                                          const float* __restrict__ kpw,
                                          const float* __restrict__ kpb) {
    __shared__ float4 kf4[K_ * 33];
    __shared__ float4 qk4[H_ * 33];
    __shared__ __align__(16) float attnS[K_ * 8];      // [k*8 + h]
    __shared__ float psum[K_ * 16];                    // [k*16 + h*2 + chalf]
    __shared__ int   idxs[K_];
    __shared__ float relx[K_], rely[K_], relz[K_];
    __shared__ float qb_s[H_];
    __shared__ unsigned char msk[K_];

    int t = threadIdx.x;
    int n = blockIdx.x;
    int isbyte = g_mask_is_byte;

    if (t < K_) {
        int i = kidx[(size_t)n * K_ + t];
        idxs[t] = i;
        unsigned char mk;
        if (isbyte) mk = (((const unsigned char*)kmask)[(size_t)n * K_ + t] != 0);
        else        mk = (((const int*)kmask)[(size_t)n * K_ + t] != 0);
        msk[t] = mk;
        relx[t] = coords[(size_t)i * 3 + 0] - coords[(size_t)n * 3 + 0];
        rely[t] = coords[(size_t)i * 3 + 1] - coords[(size_t)n * 3 + 1];
        relz[t] = coords[(size_t)i * 3 + 2] - coords[(size_t)n * 3 + 2];
    }
    if (t < H_) qb_s[t] = g_QB[(size_t)n * H_ + t];
    {
        int h = t >> 4, c2 = (t & 15) * 2;
        const float4* src = (const float4*)(g_QK + (size_t)n * (H_ * C_) + h * C_);
        qk4[h * 33 + c2]     = __ldg(src + c2);
        qk4[h * 33 + c2 + 1] = __ldg(src + c2 + 1);
    }

    int c4 = t & 31, q = t >> 5;
    float4 wa = __ldg((const float4*)(kpw + 12 * c4));
    float4 wb = __ldg((const float4*)(kpw + 12 * c4 + 4));
    float4 wc = __ldg((const float4*)(kpw + 12 * c4 + 8));
    float4 pb4 = __ldg((const float4*)(kpb + 4 * c4));
    __syncthreads();

    // gather + posemb
    #pragma unroll
    for (int kk = 0; kk < 12; kk++) {
        int k = q * 12 + kk;
        int i = idxs[k];
        float4 v = __ldg((const float4*)(vf + (size_t)i * C_) + c4);
        float rx = relx[k], ry = rely[k], rz = relz[k];
        float p0 = fmaf(rz, wa.z, fmaf(ry, wa.y, fmaf(rx, wa.x, pb4.x)));
        float p1 = fmaf(rz, wb.y, fmaf(ry, wb.x, fmaf(rx, wa.w, pb4.y)));
        float p2 = fmaf(rz, wc.x, fmaf(ry, wb.w, fmaf(rx, wb.z, pb4.z)));
        float p3 = fmaf(rz, wc.w, fmaf(ry, wc.z, fmaf(rx, wc.y, pb4.w)));
        v.x += fmaxf(p0, 0.f); v.y += fmaxf(p1, 0.f);
        v.z += fmaxf(p2, 0.f); v.w += fmaxf(p3, 0.f);
        kf4[k * 33 + c4] = v;
    }
    __syncthreads();

    // scores partials: 96 threads -> (g: head group of 4, chalf: 64 channels, key pair {kp, kp+24})
    if (t < 96) {
        int g  = t / 48;
        int rr = t - g * 48;
        int ch = rr / 24;           // uniform within quarter-warps
        int kp = rr - ch * 24;
        int cbase = ch * 16;        // in float4 units
        u64 a[8];
        #pragma unroll
        for (int i = 0; i < 8; i++) a[i] = 0;
        #pragma unroll
        for (int cc = 0; cc < 8; cc++) {        // chunks of 2 float4 = 8 channels
            ulonglong2 qr[4][2];
            #pragma unroll
            for (int j = 0; j < 4; j++) {
                qr[j][0] = *(const ulonglong2*)&qk4[(4*g+j) * 33 + cbase + 2*cc];
                qr[j][1] = *(const ulonglong2*)&qk4[(4*g+j) * 33 + cbase + 2*cc + 1];
            }
            #pragma unroll
            for (int kk = 0; kk < 2; kk++) {
                int k = kp + 24 * kk;
                ulonglong2 f0 = *(const ulonglong2*)&kf4[k * 33 + cbase + 2*cc];
                ulonglong2 f1 = *(const ulonglong2*)&kf4[k * 33 + cbase + 2*cc + 1];
                #pragma unroll
                for (int j = 0; j < 4; j++) {
                    f2(a[kk*4+j], f0.x, qr[j][0].x);
                    f2(a[kk*4+j], f0.y, qr[j][0].y);
                    f2(a[kk*4+j], f1.x, qr[j][1].x);
                    f2(a[kk*4+j], f1.y, qr[j][1].y);
                }
            }
        }
        #pragma unroll
        for (int kk = 0; kk < 2; kk++)
            #pragma unroll
            for (int j = 0; j < 4; j++) {
                float2 s = up2(a[kk*4+j]);
                psum[(kp + 24*kk) * 16 + (4*g+j) * 2 + ch] = s.x + s.y;
            }
    }
    __syncthreads();

    // combine halves -> masked scaled scores
    #pragma unroll
    for (int j = 0; j < 3; j++) {
        int s = t * 3 + j;
        int h = s / K_;
        int k = s - h * K_;
        float val = (psum[k * 16 + h * 2] + psum[k * 16 + h * 2 + 1] + qb_s[h]) * 0.25f;
        if (msk[k]) val = -1e9f;
        attnS[k * 8 + h] = val;
    }
    __syncthreads();

    // softmax: warp w -> heads 2w, 2w+1
    {
        int w = t >> 5, l = t & 31;
        #pragma unroll
        for (int hh = 0; hh < 2; hh++) {
            int h = 2 * w + hh;
            float a = attnS[l * 8 + h];
            float b = (l < 16) ? attnS[(32 + l) * 8 + h] : -3.4e38f;
            float mx = fmaxf(a, b);
            #pragma unroll
            for (int o = 16; o > 0; o >>= 1) mx = fmaxf(mx, __shfl_xor_sync(0xffffffffu, mx, o));
            float ea = __expf(a - mx);
            float eb = (l < 16) ? __expf(b - mx) : 0.f;
            float sm = ea + eb;
            #pragma unroll
            for (int o = 16; o > 0; o >>= 1) sm += __shfl_xor_sync(0xffffffffu, sm, o);
            float inv = 1.f / sm;
            attnS[l * 8 + h] = ea * inv;
            if (l < 16) attnS[(32 + l) * 8 + h] = eb * inv;
        }
    }
    __syncthreads();

    // ctxfeat: t<64 -> (g: head group of 4, cc: float4 column)
    if (t < 64) {
        int g = t >> 5, cc = t & 31;
        u64 A[4][2];
        #pragma unroll
        for (int j = 0; j < 4; j++) { A[j][0] = 0; A[j][1] = 0; }
        #pragma unroll 4
        for (int k = 0; k < K_; k++) {
            ulonglong2 f = *(const ulonglong2*)&kf4[k * 33 + cc];
            float4 a = *(const float4*)&attnS[k * 8 + 4 * g];
            u64 a0 = pk2(a.x), a1 = pk2(a.y), a2 = pk2(a.z), a3 = pk2(a.w);
            f2(A[0][0], f.x, a0); f2(A[0][1], f.y, a0);
            f2(A[1][0], f.x, a1); f2(A[1][1], f.y, a1);
            f2(A[2][0], f.x, a2); f2(A[2][1], f.y, a2);
            f2(A[3][0], f.x, a3); f2(A[3][1], f.y, a3);
        }
        float4* dst = (float4*)(g_CTXF + (size_t)n * (H_ * C_));
        #pragma unroll
        for (int j = 0; j < 4; j++) {
            float2 xy = up2(A[j][0]);
            float2 zw = up2(A[j][1]);
            dst[(4*g+j) * 32 + cc] = make_float4(xy.x, xy.y, zw.x, zw.y);
        }
    }
}

// ---------------- kernel C ----------------
__global__ void __launch_bounds__(128) kC(const float* __restrict__ vf,
                                          const float* __restrict__ ipb,
                                          const float* __restrict__ opb,
                                          const float* __restrict__ ln1g, const float* __restrict__ ln1b,
                                          const float* __restrict__ ln2g, const float* __restrict__ ln2b,
                                          const float* __restrict__ ff1b, const float* __restrict__ ff2b,
                                          const float* __restrict__ outb,
                                          const float* __restrict__ ln3g, const float* __restrict__ ln3b,
                                          float* __restrict__ out) {
    __shared__ float bufA[C_ * S_];
    __shared__ float bufC[C_ * S_];
    __shared__ float mean_s[MT], rstd_s[MT];

    int t = threadIdx.x;
    int n0 = blockIdx.x * MT;
    int h = t >> 4;

    u64 acc[16];
    float keep[MT];
    #pragma unroll
    for (int p = 0; p < 16; p++) acc[p] = 0;

    // --- ctx ---
    for (int ch = 0; ch < 8; ch++) {
        int c0 = ch * 16;
        __syncthreads();
        {
            int hh = t >> 4, cl = t & 15;
            float r[MT];
            #pragma unroll
            for (int m = 0; m < MT; m++) {
                int n = n0 + m; if (n >= N_) n = N_ - 1;
                r[m] = g_CTXF[(size_t)n * (H_ * C_) + hh * C_ + c0 + cl];
            }
            #pragma unroll
            for (int m4 = 0; m4 < 8; m4++)
                *(float4*)&bufC[t * S_ + 4 * m4] =
                    make_float4(r[4*m4], r[4*m4+1], r[4*m4+2], r[4*m4+3]);
        }
        __syncthreads();
        #pragma unroll
        for (int cl = 0; cl < 16; cl++)
            GSTEP(bufC, h * 16 + cl, g_wvT[(c0 + cl) * C_ + t], acc);
    }
    float bv = ipb[2 * C_ + t];
    __syncthreads();
    {
        float r[MT]; UNPK(acc, r);
        #pragma unroll
        for (int m4 = 0; m4 < 8; m4++)
            *(float4*)&bufC[t * S_ + 4 * m4] = make_float4(r[4*m4]+bv, r[4*m4+1]+bv,
                                                           r[4*m4+2]+bv, r[4*m4+3]+bv);
    }
    __syncthreads();

    // --- attend + residual -> LN1 ---
    #pragma unroll
    for (int p = 0; p < 16; p++) acc[p] = 0;
    for (int c = 0; c < C_; c++) GSTEP(bufC, c, g_opT[c * C_ + t], acc);
    {
        float r[MT]; UNPK(acc, r);
        float ob = opb[t];
        #pragma unroll
        for (int m = 0; m < MT; m++) {
            int n = n0 + m; if (n >= N_) n = N_ - 1;
            r[m] = vf[(size_t)n * C_ + t] + r[m] + ob;
        }
        #pragma unroll
        for (int m4 = 0; m4 < 8; m4++)
            *(float4*)&bufA[t * S_ + 4 * m4] =
                make_float4(r[4*m4], r[4*m4+1], r[4*m4+2], r[4*m4+3]);
    }
    __syncthreads();
    if (t < MT) {
        float s = 0.f, s2 = 0.f;
        for (int c = 0; c < C_; c++) { float v = bufA[c * S_ + t]; s += v; s2 = fmaf(v, v, s2); }
        float mn = s * (1.f / C_);
        mean_s[t] = mn; rstd_s[t] = rsqrtf(s2 * (1.f / C_) - mn * mn + 1e-5f);
    }
    __syncthreads();
    {
        float g = ln1g[t], b = ln1b[t];
        #pragma unroll
        for (int m = 0; m < MT; m++) {
            float v = (bufA[t * S_ + m] - mean_s[m]) * rstd_s[m] * g + b;
            bufA[t * S_ + m] = v;
            keep[m] = v;
        }
    }
    __syncthreads();

    // --- FF ---
    u64 acc2[16];
    #pragma unroll
    for (int p = 0; p < 16; p++) acc2[p] = 0;
    for (int fc = 0; fc < 2; fc++) {
        int f = fc * 128 + t;
        #pragma unroll
        for (int p = 0; p < 16; p++) acc[p] = 0;
        for (int c = 0; c < C_; c++) GSTEP(bufA, c, g_ff1T[c * FF_ + f], acc);
        float fb = ff1b[f];
        __syncthreads();
        {
            float r[MT]; UNPK(acc, r);
            #pragma unroll
            for (int m4 = 0; m4 < 8; m4++)
                *(float4*)&bufC[t * S_ + 4 * m4] =
                    make_float4(fmaxf(r[4*m4]+fb, 0.f),   fmaxf(r[4*m4+1]+fb, 0.f),
                                fmaxf(r[4*m4+2]+fb, 0.f), fmaxf(r[4*m4+3]+fb, 0.f));
        }
        __syncthreads();
        for (int fl = 0; fl < 128; fl++)
            GSTEP(bufC, fl, g_ff2T[(size_t)(fc * 128 + fl) * C_ + t], acc2);
    }
    // --- LN2 ---
    {
        float r[MT]; UNPK(acc2, r);
        float fb2 = ff2b[t];
        __syncthreads();
        #pragma unroll
        for (int m4 = 0; m4 < 8; m4++)
            *(float4*)&bufA[t * S_ + 4 * m4] =
                make_float4(keep[4*m4]+r[4*m4]+fb2,     keep[4*m4+1]+r[4*m4+1]+fb2,
                            keep[4*m4+2]+r[4*m4+2]+fb2, keep[4*m4+3]+r[4*m4+3]+fb2);
    }
    __syncthreads();
    if (t < MT) {
        float s = 0.f, s2 = 0.f;
        for (int c = 0; c < C_; c++) { float v = bufA[c * S_ + t]; s += v; s2 = fmaf(v, v, s2); }
        float mn = s * (1.f / C_);
        mean_s[t] = mn; rstd_s[t] = rsqrtf(s2 * (1.f / C_) - mn * mn + 1e-5f);
    }
    __syncthreads();
    {
        float g = ln2g[t], b = ln2b[t];
        #pragma unroll
        for (int m = 0; m < MT; m++)
            bufA[t * S_ + m] = (bufA[t * S_ + m] - mean_s[m]) * rstd_s[m] * g + b;
    }
    __syncthreads();

    // --- out projection -> LN3 -> relu ---
    #pragma unroll
    for (int p = 0; p < 16; p++) acc[p] = 0;
    for (int c = 0; c < C_; c++) GSTEP(bufA, c, g_outT[c * OUT_ + t], acc);
    {
        float r[MT]; UNPK(acc, r);
        float ob = outb[t];
        #pragma unroll
        for (int m4 = 0; m4 < 8; m4++)
            *(float4*)&bufC[t * S_ + 4 * m4] = make_float4(r[4*m4]+ob, r[4*m4+1]+ob,
                                                           r[4*m4+2]+ob, r[4*m4+3]+ob);
    }
    __syncthreads();
    if (t < MT) {
        float s = 0.f, s2 = 0.f;
        for (int c = 0; c < OUT_; c++) { float v = bufC[c * S_ + t]; s += v; s2 = fmaf(v, v, s2); }
        float mn = s * (1.f / OUT_);
        mean_s[t] = mn; rstd_s[t] = rsqrtf(s2 * (1.f / OUT_) - mn * mn + 1e-5f);
    }
    __syncthreads();
    {
        float g = ln3g[t], b = ln3b[t];
        #pragma unroll
        for (int m = 0; m < MT; m++) {
            int n = n0 + m;
            if (n < N_) {
                float v = (bufC[t * S_ + m] - mean_s[m]) * rstd_s[m] * g + b;
                out[(size_t)n * OUT_ + t] = fmaxf(v, 0.f);
            }
        }
    }
}

// ---------------- launch ----------------
extern "C" void kernel_launch(void* const* d_in, const int* in_sizes, int n_in,
                              void* d_out, int out_size) {
    const float* vf     = (const float*)d_in[0];
    const float* coords = (const float*)d_in[1];
    const int*   kidx   = (const int*)  d_in[2];
    const void*  kmask  =               d_in[3];
    const float* ipw    = (const float*)d_in[4];
    const float* ipb    = (const float*)d_in[5];
    const float* opw    = (const float*)d_in[6];
    const float* opb    = (const float*)d_in[7];
    const float* kpw    = (const float*)d_in[8];
    const float* kpb    = (const float*)d_in[9];
    const float* ln1g   = (const float*)d_in[10];
    const float* ln1b   = (const float*)d_in[11];
    const float* ln2g   = (const float*)d_in[12];
    const float* ln2b   = (const float*)d_in[13];
    const float* ff1w   = (const float*)d_in[14];
    const float* ff1b   = (const float*)d_in[15];
    const float* ff2w   = (const float*)d_in[16];
    const float* ff2b   = (const float*)d_in[17];
    const float* outw   = (const float*)d_in[18];
    const float* outb   = (const float*)d_in[19];
    const float* ln3g   = (const float*)d_in[20];
    const float* ln3b   = (const float*)d_in[21];

    kDetect<<<1, 256>>>((const int*)kmask);
    kPrep<<<(131072 + 255) / 256, 256>>>(ipw, opw, ff1w, ff2w, outw);
    kA<<<NBLK, 128>>>(vf, ipw, ipb);
    kB<<<N_, 128>>>(vf, coords, kidx, kmask, kpw, kpb);
    kC<<<NBLK, 128>>>(vf, ipb, opb, ln1g, ln1b, ln2g, ln2b,
                      ff1b, ff2b, outb, ln3g, ln3b, (float*)d_out);
}

// round 6
// speedup vs baseline: 1.8960x; 1.0810x over previous
#include <cuda_runtime.h>
#include <cstdint>
#include <cstddef>

#define N_   50000
#define K_   48
#define C_   128
#define H_   8
#define D_   16
#define FF_  256
#define OUT_ 128
#define MT   32
#define S_   36
#define NBLK ((N_ + MT - 1) / MT)

typedef unsigned long long u64;

// ---- f32x2 packed helpers (Blackwell sm_100+) ----
__device__ __forceinline__ u64 pk2(float w) {
    u64 r; asm("mov.b64 %0,{%1,%1};" : "=l"(r) : "f"(w)); return r;
}
__device__ __forceinline__ void f2(u64& d, u64 a, u64 b) {
    asm("fma.rn.f32x2 %0,%1,%2,%0;" : "+l"(d) : "l"(a), "l"(b));
}
__device__ __forceinline__ float2 up2(u64 a) {
    float2 r; asm("mov.b64 {%0,%1},%2;" : "=f"(r.x), "=f"(r.y) : "l"(a)); return r;
}

// ---------------- device scratch ----------------
__device__ float g_QK[(size_t)N_ * H_ * C_];
__device__ float g_QB[(size_t)N_ * H_];
__device__ float g_CTXF[(size_t)N_ * H_ * C_];
__device__ float g_wqT[C_ * C_];
__device__ float g_wvT[C_ * C_];
__device__ float g_opT[C_ * C_];
__device__ float g_ff1T[C_ * FF_];
__device__ float g_ff2T[FF_ * C_];
__device__ float g_outT[C_ * OUT_];
__device__ int   g_mask_is_byte;

// ---------------- mask dtype detection ----------------
__global__ void kDetect(const int* __restrict__ km) {
    __shared__ int s;
    int t = threadIdx.x;
    if (t == 0) s = 0;
    __syncthreads();
    int bad = 0;
    for (int i = t; i < 4096; i += 256)
        if (((unsigned)km[i]) > 1u) bad = 1;
    if (bad) atomicOr(&s, 1);
    __syncthreads();
    if (t == 0) g_mask_is_byte = s;
}

// ---------------- weight transposes ----------------
__global__ void kPrep(const float* __restrict__ ipw, const float* __restrict__ opw,
                      const float* __restrict__ f1w, const float* __restrict__ f2w,
                      const float* __restrict__ ow) {
    int i = blockIdx.x * blockDim.x + threadIdx.x;
    if (i < 16384) {
        int e = i >> 7, c = i & 127;
        g_wqT[c * C_ + e] = ipw[e * C_ + c];
    } else if (i < 32768) {
        int j = i - 16384; int e = j >> 7, c = j & 127;
        g_wvT[c * C_ + e] = ipw[(2 * C_ + e) * C_ + c];
    } else if (i < 49152) {
        int j = i - 32768; int e = j >> 7, c = j & 127;
        g_opT[c * C_ + e] = opw[e * C_ + c];
    } else if (i < 81920) {
        int j = i - 49152; int f = j >> 7, c = j & 127;
        g_ff1T[c * FF_ + f] = f1w[f * C_ + c];
    } else if (i < 114688) {
        int j = i - 81920; int e = j >> 8, f = j & 255;
        g_ff2T[f * C_ + e] = f2w[e * FF_ + f];
    } else if (i < 131072) {
        int j = i - 114688; int o = j >> 7, c = j & 127;
        g_outT[c * OUT_ + o] = ow[o * C_ + c];
    }
}

// packed-GEMM step: ACC (u64[16]) += BUF[ROW, 0..31] * W
#define GSTEP(BUF, ROW, W, ACC) do {                                       \
    u64 w2_ = pk2(W);                                                      \
    _Pragma("unroll")                                                      \
    for (int p_ = 0; p_ < 8; p_++) {                                       \
        ulonglong2 v_ = *(const ulonglong2*)&(BUF)[(ROW) * S_ + 4 * p_];   \
        f2((ACC)[2 * p_],     v_.x, w2_);                                  \
        f2((ACC)[2 * p_ + 1], v_.y, w2_);                                  \
    } } while (0)

// unpack u64[16] accumulators into float[32]
#define UNPK(ACC, R) do {                                                  \
    _Pragma("unroll")                                                      \
    for (int p_ = 0; p_ < 16; p_++) {                                      \
        float2 s_ = up2((ACC)[p_]);                                        \
        (R)[2 * p_] = s_.x; (R)[2 * p_ + 1] = s_.y;                        \
    } } while (0)

// ---------------- kernel A ----------------
__global__ void __launch_bounds__(128) kA(const float* __restrict__ vf,
                                          const float* __restrict__ ipw,
                                          const float* __restrict__ ipb) {
    __shared__ float vsT[C_ * S_];
    __shared__ float QsT[C_ * S_];
    int t = threadIdx.x;
    int n0 = blockIdx.x * MT;

    float r[MT];
    #pragma unroll
    for (int m = 0; m < MT; m++) {
        int n = n0 + m; if (n >= N_) n = N_ - 1;
        r[m] = vf[(size_t)n * C_ + t];
    }
    #pragma unroll
    for (int m4 = 0; m4 < 8; m4++)
        *(float4*)&vsT[t * S_ + 4 * m4] = make_float4(r[4*m4], r[4*m4+1], r[4*m4+2], r[4*m4+3]);
    __syncthreads();

    u64 acc[16];
    #pragma unroll
    for (int p = 0; p < 16; p++) acc[p] = 0;
    for (int c = 0; c < C_; c++) GSTEP(vsT, c, g_wqT[c * C_ + t], acc);
    {
        float q[MT]; UNPK(acc, q);
        float bq = ipb[t];
        #pragma unroll
        for (int m4 = 0; m4 < 8; m4++)
            *(float4*)&QsT[t * S_ + 4 * m4] = make_float4(q[4*m4]+bq, q[4*m4+1]+bq,
                                                          q[4*m4+2]+bq, q[4*m4+3]+bq);
    }
    __syncthreads();

    for (int h = 0; h < H_; h++) {
        #pragma unroll
        for (int p = 0; p < 16; p++) acc[p] = 0;
        #pragma unroll
        for (int d = 0; d < D_; d++) {
            int e = h * D_ + d;
            GSTEP(QsT, e, ipw[(size_t)(C_ + e) * C_ + t], acc);
        }
        float q[MT]; UNPK(acc, q);
        #pragma unroll
        for (int m = 0; m < MT; m++) {
            int n = n0 + m;
            if (n < N_) g_QK[(size_t)n * (H_ * C_) + h * C_ + t] = q[m];
        }
    }
    if (t < MT) {
        int n = n0 + t;
        if (n < N_) {
            for (int h = 0; h < H_; h++) {
                float s = 0.f;
                for (int d = 0; d < D_; d++) {
                    int e = h * D_ + d;
                    s = fmaf(QsT[e * S_ + t], ipb[C_ + e], s);
                }
                g_QB[(size_t)n * H_ + h] = s;
            }
        }
    }
}

// ---------------- kernel B ----------------
__global__ void __launch_bounds__(128) kB(const float* __restrict__ vf,
                                          const float* __restrict__ coords,
                                          const int* __restrict__ kidx,
                                          const void* __restrict__ kmask,
                                          const float* __restrict__ kpw,
                                          const float* __restrict__ kpb) {
    __shared__ float4 kf4[K_ * 33];
    __shared__ float4 qk4[H_ * 33];
    __shared__ __align__(16) float attnS[K_ * 8];      // [k*8 + h]
    __shared__ int   idxs[K_];
    __shared__ float relx[K_], rely[K_], relz[K_];
    __shared__ float qb_s[H_];
    __shared__ unsigned char msk[K_];

    int t = threadIdx.x;
    int n = blockIdx.x;
    int isbyte = g_mask_is_byte;

    if (t < K_) {
        int i = kidx[(size_t)n * K_ + t];
        idxs[t] = i;
        unsigned char mk;
        if (isbyte) mk = (((const unsigned char*)kmask)[(size_t)n * K_ + t] != 0);
        else        mk = (((const int*)kmask)[(size_t)n * K_ + t] != 0);
        msk[t] = mk;
        relx[t] = coords[(size_t)i * 3 + 0] - coords[(size_t)n * 3 + 0];
        rely[t] = coords[(size_t)i * 3 + 1] - coords[(size_t)n * 3 + 1];
        relz[t] = coords[(size_t)i * 3 + 2] - coords[(size_t)n * 3 + 2];
    }
    if (t < H_) qb_s[t] = g_QB[(size_t)n * H_ + t];
    {
        int h = t >> 4, c2 = (t & 15) * 2;
        const float4* src = (const float4*)(g_QK + (size_t)n * (H_ * C_) + h * C_);
        qk4[h * 33 + c2]     = __ldg(src + c2);
        qk4[h * 33 + c2 + 1] = __ldg(src + c2 + 1);
    }

    int c4 = t & 31, q = t >> 5;
    float4 wa = __ldg((const float4*)(kpw + 12 * c4));
    float4 wb = __ldg((const float4*)(kpw + 12 * c4 + 4));
    float4 wc = __ldg((const float4*)(kpw + 12 * c4 + 8));
    float4 pb4 = __ldg((const float4*)(kpb + 4 * c4));
    __syncthreads();

    // gather + posemb: 4 channels x 12 keys per thread
    #pragma unroll
    for (int kk = 0; kk < 12; kk++) {
        int k = q * 12 + kk;
        int i = idxs[k];
        float4 v = __ldg((const float4*)(vf + (size_t)i * C_) + c4);
        float rx = relx[k], ry = rely[k], rz = relz[k];
        float p0 = fmaf(rz, wa.z, fmaf(ry, wa.y, fmaf(rx, wa.x, pb4.x)));
        float p1 = fmaf(rz, wb.y, fmaf(ry, wb.x, fmaf(rx, wa.w, pb4.y)));
        float p2 = fmaf(rz, wc.x, fmaf(ry, wb.w, fmaf(rx, wb.z, pb4.z)));
        float p3 = fmaf(rz, wc.w, fmaf(ry, wc.z, fmaf(rx, wc.y, pb4.w)));
        v.x += fmaxf(p0, 0.f); v.y += fmaxf(p1, 0.f);
        v.z += fmaxf(p2, 0.f); v.w += fmaxf(p3, 0.f);
        kf4[k * 33 + c4] = v;
    }
    __syncthreads();

    // scores: 48 threads -> (g: head quad, kp: key with pair kp+24)
    // per c-iter: 2 kf loads + 4 qk broadcasts -> 8 dots (0.75 LDS/dot)
    if (t < 48) {
        int g  = t / 24;                 // uniform within quarter-warps (24 % 8 == 0)
        int kp = t - g * 24;
        u64 a[2][4];
        #pragma unroll
        for (int kk = 0; kk < 2; kk++)
            #pragma unroll
            for (int j = 0; j < 4; j++) a[kk][j] = 0;
        #pragma unroll 4
        for (int c = 0; c < 32; c++) {
            ulonglong2 f0 = *(const ulonglong2*)&kf4[kp * 33 + c];
            ulonglong2 f1 = *(const ulonglong2*)&kf4[(kp + 24) * 33 + c];
            #pragma unroll
            for (int j = 0; j < 4; j++) {
                ulonglong2 qv = *(const ulonglong2*)&qk4[(4 * g + j) * 33 + c];
                f2(a[0][j], f0.x, qv.x); f2(a[0][j], f0.y, qv.y);
                f2(a[1][j], f1.x, qv.x); f2(a[1][j], f1.y, qv.y);
            }
        }
        #pragma unroll
        for (int kk = 0; kk < 2; kk++) {
            int k = kp + 24 * kk;
            bool mk = msk[k] != 0;
            #pragma unroll
            for (int j = 0; j < 4; j++) {
                int h = 4 * g + j;
                float2 s = up2(a[kk][j]);
                float val = (s.x + s.y + qb_s[h]) * 0.25f;
                attnS[k * 8 + h] = mk ? -1e9f : val;
            }
        }
    }
    __syncthreads();

    // softmax: warp w -> heads 2w, 2w+1
    {
        int w = t >> 5, l = t & 31;
        #pragma unroll
        for (int hh = 0; hh < 2; hh++) {
            int h = 2 * w + hh;
            float a = attnS[l * 8 + h];
            float b = (l < 16) ? attnS[(32 + l) * 8 + h] : -3.4e38f;
            float mx = fmaxf(a, b);
            #pragma unroll
            for (int o = 16; o > 0; o >>= 1) mx = fmaxf(mx, __shfl_xor_sync(0xffffffffu, mx, o));
            float ea = __expf(a - mx);
            float eb = (l < 16) ? __expf(b - mx) : 0.f;
            float sm = ea + eb;
            #pragma unroll
            for (int o = 16; o > 0; o >>= 1) sm += __shfl_xor_sync(0xffffffffu, sm, o);
            float inv = 1.f / sm;
            attnS[l * 8 + h] = ea * inv;
            if (l < 16) attnS[(32 + l) * 8 + h] = eb * inv;
        }
    }
    __syncthreads();

    // ctxfeat: t<64 -> (g: head group of 4, cc: float4 column)
    if (t < 64) {
        int g = t >> 5, cc = t & 31;
        u64 A[4][2];
        #pragma unroll
        for (int j = 0; j < 4; j++) { A[j][0] = 0; A[j][1] = 0; }
        #pragma unroll 4
        for (int k = 0; k < K_; k++) {
            ulonglong2 f = *(const ulonglong2*)&kf4[k * 33 + cc];
            float4 a = *(const float4*)&attnS[k * 8 + 4 * g];
            u64 a0 = pk2(a.x), a1 = pk2(a.y), a2 = pk2(a.z), a3 = pk2(a.w);
            f2(A[0][0], f.x, a0); f2(A[0][1], f.y, a0);
            f2(A[1][0], f.x, a1); f2(A[1][1], f.y, a1);
            f2(A[2][0], f.x, a2); f2(A[2][1], f.y, a2);
            f2(A[3][0], f.x, a3); f2(A[3][1], f.y, a3);
        }
        float4* dst = (float4*)(g_CTXF + (size_t)n * (H_ * C_));
        #pragma unroll
        for (int j = 0; j < 4; j++) {
            float2 xy = up2(A[j][0]);
            float2 zw = up2(A[j][1]);
            dst[(4*g+j) * 32 + cc] = make_float4(xy.x, xy.y, zw.x, zw.y);
        }
    }
}

// ---------------- kernel C ----------------
__global__ void __launch_bounds__(128) kC(const float* __restrict__ vf,
                                          const float* __restrict__ ipb,
                                          const float* __restrict__ opb,
                                          const float* __restrict__ ln1g, const float* __restrict__ ln1b,
                                          const float* __restrict__ ln2g, const float* __restrict__ ln2b,
                                          const float* __restrict__ ff1b, const float* __restrict__ ff2b,
                                          const float* __restrict__ outb,
                                          const float* __restrict__ ln3g, const float* __restrict__ ln3b,
                                          float* __restrict__ out) {
    __shared__ float bufA[C_ * S_];
    __shared__ float bufC[C_ * S_];
    __shared__ float mean_s[MT], rstd_s[MT];

    int t = threadIdx.x;
    int n0 = blockIdx.x * MT;
    int h = t >> 4;

    u64 acc[16];
    float keep[MT];
    #pragma unroll
    for (int p = 0; p < 16; p++) acc[p] = 0;

    // --- ctx ---
    for (int ch = 0; ch < 8; ch++) {
        int c0 = ch * 16;
        __syncthreads();
        {
            int hh = t >> 4, cl = t & 15;
            float r[MT];
            #pragma unroll
            for (int m = 0; m < MT; m++) {
                int n = n0 + m; if (n >= N_) n = N_ - 1;
                r[m] = g_CTXF[(size_t)n * (H_ * C_) + hh * C_ + c0 + cl];
            }
            #pragma unroll
            for (int m4 = 0; m4 < 8; m4++)
                *(float4*)&bufC[t * S_ + 4 * m4] =
                    make_float4(r[4*m4], r[4*m4+1], r[4*m4+2], r[4*m4+3]);
        }
        __syncthreads();
        #pragma unroll
        for (int cl = 0; cl < 16; cl++)
            GSTEP(bufC, h * 16 + cl, g_wvT[(c0 + cl) * C_ + t], acc);
    }
    float bv = ipb[2 * C_ + t];
    __syncthreads();
    {
        float r[MT]; UNPK(acc, r);
        #pragma unroll
        for (int m4 = 0; m4 < 8; m4++)
            *(float4*)&bufC[t * S_ + 4 * m4] = make_float4(r[4*m4]+bv, r[4*m4+1]+bv,
                                                           r[4*m4+2]+bv, r[4*m4+3]+bv);
    }
    __syncthreads();

    // --- attend + residual -> LN1 ---
    #pragma unroll
    for (int p = 0; p < 16; p++) acc[p] = 0;
    for (int c = 0; c < C_; c++) GSTEP(bufC, c, g_opT[c * C_ + t], acc);
    {
        float r[MT]; UNPK(acc, r);
        float ob = opb[t];
        #pragma unroll
        for (int m = 0; m < MT; m++) {
            int n = n0 + m; if (n >= N_) n = N_ - 1;
            r[m] = vf[(size_t)n * C_ + t] + r[m] + ob;
        }
        #pragma unroll
        for (int m4 = 0; m4 < 8; m4++)
            *(float4*)&bufA[t * S_ + 4 * m4] =
                make_float4(r[4*m4], r[4*m4+1], r[4*m4+2], r[4*m4+3]);
    }
    __syncthreads();
    if (t < MT) {
        float s = 0.f, s2 = 0.f;
        for (int c = 0; c < C_; c++) { float v = bufA[c * S_ + t]; s += v; s2 = fmaf(v, v, s2); }
        float mn = s * (1.f / C_);
        mean_s[t] = mn; rstd_s[t] = rsqrtf(s2 * (1.f / C_) - mn * mn + 1e-5f);
    }
    __syncthreads();
    {
        float g = ln1g[t], b = ln1b[t];
        #pragma unroll
        for (int m = 0; m < MT; m++) {
            float v = (bufA[t * S_ + m] - mean_s[m]) * rstd_s[m] * g + b;
            bufA[t * S_ + m] = v;
            keep[m] = v;
        }
    }
    __syncthreads();

    // --- FF ---
    u64 acc2[16];
    #pragma unroll
    for (int p = 0; p < 16; p++) acc2[p] = 0;
    for (int fc = 0; fc < 2; fc++) {
        int f = fc * 128 + t;
        #pragma unroll
        for (int p = 0; p < 16; p++) acc[p] = 0;
        for (int c = 0; c < C_; c++) GSTEP(bufA, c, g_ff1T[c * FF_ + f], acc);
        float fb = ff1b[f];
        __syncthreads();
        {
            float r[MT]; UNPK(acc, r);
            #pragma unroll
            for (int m4 = 0; m4 < 8; m4++)
                *(float4*)&bufC[t * S_ + 4 * m4] =
                    make_float4(fmaxf(r[4*m4]+fb, 0.f),   fmaxf(r[4*m4+1]+fb, 0.f),
                                fmaxf(r[4*m4+2]+fb, 0.f), fmaxf(r[4*m4+3]+fb, 0.f));
        }
        __syncthreads();
        for (int fl = 0; fl < 128; fl++)
            GSTEP(bufC, fl, g_ff2T[(size_t)(fc * 128 + fl) * C_ + t], acc2);
    }
    // --- LN2 ---
    {
        float r[MT]; UNPK(acc2, r);
        float fb2 = ff2b[t];
        __syncthreads();
        #pragma unroll
        for (int m4 = 0; m4 < 8; m4++)
            *(float4*)&bufA[t * S_ + 4 * m4] =
                make_float4(keep[4*m4]+r[4*m4]+fb2,     keep[4*m4+1]+r[4*m4+1]+fb2,
                            keep[4*m4+2]+r[4*m4+2]+fb2, keep[4*m4+3]+r[4*m4+3]+fb2);
    }
    __syncthreads();
    if (t < MT) {
        float s = 0.f, s2 = 0.f;
        for (int c = 0; c < C_; c++) { float v = bufA[c * S_ + t]; s += v; s2 = fmaf(v, v, s2); }
        float mn = s * (1.f / C_);
        mean_s[t] = mn; rstd_s[t] = rsqrtf(s2 * (1.f / C_) - mn * mn + 1e-5f);
    }
    __syncthreads();
    {
        float g = ln2g[t], b = ln2b[t];
        #pragma unroll
        for (int m = 0; m < MT; m++)
            bufA[t * S_ + m] = (bufA[t * S_ + m] - mean_s[m]) * rstd_s[m] * g + b;
    }
    __syncthreads();

    // --- out projection -> LN3 -> relu ---
    #pragma unroll
    for (int p = 0; p < 16; p++) acc[p] = 0;
    for (int c = 0; c < C_; c++) GSTEP(bufA, c, g_outT[c * OUT_ + t], acc);
    {
        float r[MT]; UNPK(acc, r);
        float ob = outb[t];
        #pragma unroll
        for (int m4 = 0; m4 < 8; m4++)
            *(float4*)&bufC[t * S_ + 4 * m4] = make_float4(r[4*m4]+ob, r[4*m4+1]+ob,
                                                           r[4*m4+2]+ob, r[4*m4+3]+ob);
    }
    __syncthreads();
    if (t < MT) {
        float s = 0.f, s2 = 0.f;
        for (int c = 0; c < OUT_; c++) { float v = bufC[c * S_ + t]; s += v; s2 = fmaf(v, v, s2); }
        float mn = s * (1.f / OUT_);
        mean_s[t] = mn; rstd_s[t] = rsqrtf(s2 * (1.f / OUT_) - mn * mn + 1e-5f);
    }
    __syncthreads();
    {
        float g = ln3g[t], b = ln3b[t];
        #pragma unroll
        for (int m = 0; m < MT; m++) {
            int n = n0 + m;
            if (n < N_) {
                float v = (bufC[t * S_ + m] - mean_s[m]) * rstd_s[m] * g + b;
                out[(size_t)n * OUT_ + t] = fmaxf(v, 0.f);
            }
        }
    }
}

// ---------------- launch ----------------
extern "C" void kernel_launch(void* const* d_in, const int* in_sizes, int n_in,
                              void* d_out, int out_size) {
    const float* vf     = (const float*)d_in[0];
    const float* coords = (const float*)d_in[1];
    const int*   kidx   = (const int*)  d_in[2];
    const void*  kmask  =               d_in[3];
    const float* ipw    = (const float*)d_in[4];
    const float* ipb    = (const float*)d_in[5];
    const float* opw    = (const float*)d_in[6];
    const float* opb    = (const float*)d_in[7];
    const float* kpw    = (const float*)d_in[8];
    const float* kpb    = (const float*)d_in[9];
    const float* ln1g   = (const float*)d_in[10];
    const float* ln1b   = (const float*)d_in[11];
    const float* ln2g   = (const float*)d_in[12];
    const float* ln2b   = (const float*)d_in[13];
    const float* ff1w   = (const float*)d_in[14];
    const float* ff1b   = (const float*)d_in[15];
    const float* ff2w   = (const float*)d_in[16];
    const float* ff2b   = (const float*)d_in[17];
    const float* outw   = (const float*)d_in[18];
    const float* outb   = (const float*)d_in[19];
    const float* ln3g   = (const float*)d_in[20];
    const float* ln3b   = (const float*)d_in[21];

    kDetect<<<1, 256>>>((const int*)kmask);
    kPrep<<<(131072 + 255) / 256, 256>>>(ipw, opw, ff1w, ff2w, outw);
    kA<<<NBLK, 128>>>(vf, ipw, ipb);
    kB<<<N_, 128>>>(vf, coords, kidx, kmask, kpw, kpb);
    kC<<<NBLK, 128>>>(vf, ipb, opb, ln1g, ln1b, ln2g, ln2b,
                      ff1b, ff2b, outb, ln3g, ln3b, (float*)d_out);
}

// round 7
// speedup vs baseline: 2.2330x; 1.1778x over previous
#include <cuda_runtime.h>
#include <cstdint>
#include <cstddef>

#define N_   50000
#define K_   48
#define C_   128
#define H_   8
#define D_   16
#define FF_  256
#define OUT_ 128
#define MT   32
#define S_   36
#define NBLK ((N_ + MT - 1) / MT)

typedef unsigned long long u64;

// ---- f32x2 packed helpers (Blackwell sm_100+) ----
__device__ __forceinline__ u64 pk2(float w) {
    u64 r; asm("mov.b64 %0,{%1,%1};" : "=l"(r) : "f"(w)); return r;
}
__device__ __forceinline__ void f2(u64& d, u64 a, u64 b) {
    asm("fma.rn.f32x2 %0,%1,%2,%0;" : "+l"(d) : "l"(a), "l"(b));
}
__device__ __forceinline__ float2 up2(u64 a) {
    float2 r; asm("mov.b64 {%0,%1},%2;" : "=f"(r.x), "=f"(r.y) : "l"(a)); return r;
}

// ---------------- device scratch ----------------
__device__ float g_QK[(size_t)N_ * H_ * C_];
__device__ float g_QB[(size_t)N_ * H_];
__device__ float g_CTXF[(size_t)N_ * H_ * C_];
__device__ float g_wqT[C_ * C_];
__device__ float g_wvT[C_ * C_];
__device__ float g_opT[C_ * C_];
__device__ float g_ff1T[C_ * FF_];
__device__ float g_ff2T[FF_ * C_];
__device__ float g_outT[C_ * OUT_];
__device__ int   g_mask_is_byte;

// ---------------- mask dtype detection ----------------
__global__ void kDetect(const int* __restrict__ km) {
    __shared__ int s;
    int t = threadIdx.x;
    if (t == 0) s = 0;
    __syncthreads();
    int bad = 0;
    for (int i = t; i < 4096; i += 256)
        if (((unsigned)km[i]) > 1u) bad = 1;
    if (bad) atomicOr(&s, 1);
    __syncthreads();
    if (t == 0) g_mask_is_byte = s;
}

// ---------------- weight transposes ----------------
__global__ void kPrep(const float* __restrict__ ipw, const float* __restrict__ opw,
                      const float* __restrict__ f1w, const float* __restrict__ f2w,
                      const float* __restrict__ ow) {
    int i = blockIdx.x * blockDim.x + threadIdx.x;
    if (i < 16384) {
        int e = i >> 7, c = i & 127;
        g_wqT[c * C_ + e] = ipw[e * C_ + c];
    } else if (i < 32768) {
        int j = i - 16384; int e = j >> 7, c = j & 127;
        g_wvT[c * C_ + e] = ipw[(2 * C_ + e) * C_ + c];
    } else if (i < 49152) {
        int j = i - 32768; int e = j >> 7, c = j & 127;
        g_opT[c * C_ + e] = opw[e * C_ + c];
    } else if (i < 81920) {
        int j = i - 49152; int f = j >> 7, c = j & 127;
        g_ff1T[c * FF_ + f] = f1w[f * C_ + c];
    } else if (i < 114688) {
        int j = i - 81920; int e = j >> 8, f = j & 255;
        g_ff2T[f * C_ + e] = f2w[e * FF_ + f];
    } else if (i < 131072) {
        int j = i - 114688; int o = j >> 7, c = j & 127;
        g_outT[c * OUT_ + o] = ow[o * C_ + c];
    }
}

// ---- tiled-GEMM helpers: thread covers ch = ch0..ch0+3, m = mg8..mg8+7 ----
#define ZACC(A) do { _Pragma("unroll") for (int j_=0;j_<4;j_++) { \
    _Pragma("unroll") for (int p_=0;p_<4;p_++) (A)[j_][p_] = 0; } } while (0)

#define G2STEP(BUF, ROW, W4, ACC) do {                                          \
    ulonglong2 x01_ = *(const ulonglong2*)&(BUF)[(ROW)*S_ + mg8];               \
    ulonglong2 x23_ = *(const ulonglong2*)&(BUF)[(ROW)*S_ + mg8 + 4];           \
    u64 w0_=pk2((W4).x), w1_=pk2((W4).y), w2_=pk2((W4).z), w3_=pk2((W4).w);     \
    f2((ACC)[0][0],x01_.x,w0_); f2((ACC)[0][1],x01_.y,w0_);                     \
    f2((ACC)[0][2],x23_.x,w0_); f2((ACC)[0][3],x23_.y,w0_);                     \
    f2((ACC)[1][0],x01_.x,w1_); f2((ACC)[1][1],x01_.y,w1_);                     \
    f2((ACC)[1][2],x23_.x,w1_); f2((ACC)[1][3],x23_.y,w1_);                     \
    f2((ACC)[2][0],x01_.x,w2_); f2((ACC)[2][1],x01_.y,w2_);                     \
    f2((ACC)[2][2],x23_.x,w2_); f2((ACC)[2][3],x23_.y,w2_);                     \
    f2((ACC)[3][0],x01_.x,w3_); f2((ACC)[3][1],x01_.y,w3_);                     \
    f2((ACC)[3][2],x23_.x,w3_); f2((ACC)[3][3],x23_.y,w3_);                     \
} while (0)

#define STORE4(BUF, ACC, B4PTR, RELU) do {                                      \
    float4 b4_ = (B4PTR)[og];                                                   \
    float bj_[4] = {b4_.x, b4_.y, b4_.z, b4_.w};                                \
    _Pragma("unroll") for (int j_=0;j_<4;j_++) {                                \
      _Pragma("unroll") for (int p_=0;p_<4;p_++) {                              \
        float2 s_ = up2((ACC)[j_][p_]);                                         \
        s_.x += bj_[j_]; s_.y += bj_[j_];                                       \
        if (RELU) { s_.x = fmaxf(s_.x, 0.f); s_.y = fmaxf(s_.y, 0.f); }         \
        *(float2*)&(BUF)[(ch0+j_)*S_ + mg8 + 2*p_] = s_;                        \
      } }                                                                       \
} while (0)

// ---------------- kernel A ----------------
__global__ void __launch_bounds__(128) kA(const float* __restrict__ vf,
                                          const float* __restrict__ ipw,
                                          const float* __restrict__ ipb) {
    __shared__ float vsT[C_ * S_];
    __shared__ float QsT[C_ * S_];
    int t = threadIdx.x;
    int n0 = blockIdx.x * MT;
    int mg = t & 3, og = t >> 2;
    int mg8 = mg * 8, ch0 = og * 4;

    // stage vf (thread t owns channel t)
    #pragma unroll
    for (int m4 = 0; m4 < 8; m4++) {
        float a[4];
        #pragma unroll
        for (int j = 0; j < 4; j++) {
            int n = n0 + 4*m4 + j; if (n >= N_) n = N_ - 1;
            a[j] = vf[(size_t)n * C_ + t];
        }
        *(float4*)&vsT[t * S_ + 4*m4] = make_float4(a[0], a[1], a[2], a[3]);
    }
    __syncthreads();

    u64 acc[4][4];
    ZACC(acc);
    for (int c = 0; c < C_; c++) {
        float4 w4 = *(const float4*)&g_wqT[c * C_ + ch0];
        G2STEP(vsT, c, w4, acc);
    }
    STORE4(QsT, acc, (const float4*)ipb, false);
    __syncthreads();

    for (int h = 0; h < H_; h++) {
        ZACC(acc);
        #pragma unroll
        for (int d = 0; d < D_; d++) {
            int e = h * D_ + d;
            float4 w4 = *(const float4*)&ipw[(size_t)(C_ + e) * C_ + ch0];
            G2STEP(QsT, e, w4, acc);
        }
        #pragma unroll
        for (int j = 0; j < 4; j++)
            #pragma unroll
            for (int p = 0; p < 4; p++) {
                float2 s = up2(acc[j][p]);
                int m0 = mg8 + 2*p;
                int na = n0 + m0, nb = n0 + m0 + 1;
                if (na < N_) g_QK[(size_t)na * (H_*C_) + h * C_ + ch0 + j] = s.x;
                if (nb < N_) g_QK[(size_t)nb * (H_*C_) + h * C_ + ch0 + j] = s.y;
            }
    }
    if (t < MT) {
        int n = n0 + t;
        if (n < N_) {
            for (int h = 0; h < H_; h++) {
                float s = 0.f;
                for (int d = 0; d < D_; d++) {
                    int e = h * D_ + d;
                    s = fmaf(QsT[e * S_ + t], ipb[C_ + e], s);
                }
                g_QB[(size_t)n * H_ + h] = s;
            }
        }
    }
}

// ---------------- kernel B ----------------
__global__ void __launch_bounds__(128) kB(const float* __restrict__ vf,
                                          const float* __restrict__ coords,
                                          const int* __restrict__ kidx,
                                          const void* __restrict__ kmask,
                                          const float* __restrict__ kpw,
                                          const float* __restrict__ kpb) {
    __shared__ float4 kf4[K_ * 33];
    __shared__ float4 qk4[H_ * 33];
    __shared__ __align__(16) float attnS[K_ * 8];      // [k*8 + h]
    __shared__ int   idxs[K_];
    __shared__ float relx[K_], rely[K_], relz[K_];
    __shared__ float qb_s[H_];
    __shared__ unsigned char msk[K_];

    int t = threadIdx.x;
    int n = blockIdx.x;
    int isbyte = g_mask_is_byte;

    if (t < K_) {
        int i = kidx[(size_t)n * K_ + t];
        idxs[t] = i;
        unsigned char mk;
        if (isbyte) mk = (((const unsigned char*)kmask)[(size_t)n * K_ + t] != 0);
        else        mk = (((const int*)kmask)[(size_t)n * K_ + t] != 0);
        msk[t] = mk;
        relx[t] = coords[(size_t)i * 3 + 0] - coords[(size_t)n * 3 + 0];
        rely[t] = coords[(size_t)i * 3 + 1] - coords[(size_t)n * 3 + 1];
        relz[t] = coords[(size_t)i * 3 + 2] - coords[(size_t)n * 3 + 2];
    }
    if (t < H_) qb_s[t] = g_QB[(size_t)n * H_ + t];
    {
        int h = t >> 4, c2 = (t & 15) * 2;
        const float4* src = (const float4*)(g_QK + (size_t)n * (H_ * C_) + h * C_);
        qk4[h * 33 + c2]     = __ldg(src + c2);
        qk4[h * 33 + c2 + 1] = __ldg(src + c2 + 1);
    }

    int c4 = t & 31, q = t >> 5;
    float4 wa = __ldg((const float4*)(kpw + 12 * c4));
    float4 wb = __ldg((const float4*)(kpw + 12 * c4 + 4));
    float4 wc = __ldg((const float4*)(kpw + 12 * c4 + 8));
    float4 pb4 = __ldg((const float4*)(kpb + 4 * c4));
    __syncthreads();

    // gather + posemb: 4 channels x 12 keys per thread
    #pragma unroll
    for (int kk = 0; kk < 12; kk++) {
        int k = q * 12 + kk;
        int i = idxs[k];
        float4 v = __ldg((const float4*)(vf + (size_t)i * C_) + c4);
        float rx = relx[k], ry = rely[k], rz = relz[k];
        float p0 = fmaf(rz, wa.z, fmaf(ry, wa.y, fmaf(rx, wa.x, pb4.x)));
        float p1 = fmaf(rz, wb.y, fmaf(ry, wb.x, fmaf(rx, wa.w, pb4.y)));
        float p2 = fmaf(rz, wc.x, fmaf(ry, wb.w, fmaf(rx, wb.z, pb4.z)));
        float p3 = fmaf(rz, wc.w, fmaf(ry, wc.z, fmaf(rx, wc.y, pb4.w)));
        v.x += fmaxf(p0, 0.f); v.y += fmaxf(p1, 0.f);
        v.z += fmaxf(p2, 0.f); v.w += fmaxf(p3, 0.f);
        kf4[k * 33 + c4] = v;
    }
    __syncthreads();

    // scores: one warp; thread -> (kp = t>>1: keys kp, kp+16, kp+32; g = t&1: heads 4g..4g+3)
    // per c-iter: 3 kf + 4 qk loads -> 12 dots (0.58 LDS/dot)
    if (t < 32) {
        int g  = t & 1;
        int kp = t >> 1;
        u64 a[3][4];
        #pragma unroll
        for (int kk = 0; kk < 3; kk++)
            #pragma unroll
            for (int j = 0; j < 4; j++) a[kk][j] = 0;
        #pragma unroll 4
        for (int c = 0; c < 32; c++) {
            ulonglong2 f0 = *(const ulonglong2*)&kf4[kp * 33 + c];
            ulonglong2 f1 = *(const ulonglong2*)&kf4[(kp + 16) * 33 + c];
            ulonglong2 fv = *(const ulonglong2*)&kf4[(kp + 32) * 33 + c];
            #pragma unroll
            for (int j = 0; j < 4; j++) {
                ulonglong2 qv = *(const ulonglong2*)&qk4[(4 * g + j) * 33 + c];
                f2(a[0][j], f0.x, qv.x); f2(a[0][j], f0.y, qv.y);
                f2(a[1][j], f1.x, qv.x); f2(a[1][j], f1.y, qv.y);
                f2(a[2][j], fv.x, qv.x); f2(a[2][j], fv.y, qv.y);
            }
        }
        #pragma unroll
        for (int kk = 0; kk < 3; kk++) {
            int k = kp + 16 * kk;
            bool mk = msk[k] != 0;
            #pragma unroll
            for (int j = 0; j < 4; j++) {
                int h = 4 * g + j;
                float2 s = up2(a[kk][j]);
                float val = (s.x + s.y + qb_s[h]) * 0.25f;
                attnS[k * 8 + h] = mk ? -1e9f : val;
            }
        }
    }
    __syncthreads();

    // softmax: warp w -> heads 2w, 2w+1
    {
        int w = t >> 5, l = t & 31;
        #pragma unroll
        for (int hh = 0; hh < 2; hh++) {
            int h = 2 * w + hh;
            float a = attnS[l * 8 + h];
            float b = (l < 16) ? attnS[(32 + l) * 8 + h] : -3.4e38f;
            float mx = fmaxf(a, b);
            #pragma unroll
            for (int o = 16; o > 0; o >>= 1) mx = fmaxf(mx, __shfl_xor_sync(0xffffffffu, mx, o));
            float ea = __expf(a - mx);
            float eb = (l < 16) ? __expf(b - mx) : 0.f;
            float sm = ea + eb;
            #pragma unroll
            for (int o = 16; o > 0; o >>= 1) sm += __shfl_xor_sync(0xffffffffu, sm, o);
            float inv = 1.f / sm;
            attnS[l * 8 + h] = ea * inv;
            if (l < 16) attnS[(32 + l) * 8 + h] = eb * inv;
        }
    }
    __syncthreads();

    // ctxfeat: one warp; thread -> float4 column cc, all 8 heads
    if (t < 32) {
        int cc = t;
        u64 A[8][2];
        #pragma unroll
        for (int j = 0; j < 8; j++) { A[j][0] = 0; A[j][1] = 0; }
        #pragma unroll 4
        for (int k = 0; k < K_; k++) {
            ulonglong2 f = *(const ulonglong2*)&kf4[k * 33 + cc];
            float4 aA = *(const float4*)&attnS[k * 8];
            float4 aB = *(const float4*)&attnS[k * 8 + 4];
            u64 a0 = pk2(aA.x), a1 = pk2(aA.y), a2 = pk2(aA.z), a3 = pk2(aA.w);
            u64 a4 = pk2(aB.x), a5 = pk2(aB.y), a6 = pk2(aB.z), a7 = pk2(aB.w);
            f2(A[0][0], f.x, a0); f2(A[0][1], f.y, a0);
            f2(A[1][0], f.x, a1); f2(A[1][1], f.y, a1);
            f2(A[2][0], f.x, a2); f2(A[2][1], f.y, a2);
            f2(A[3][0], f.x, a3); f2(A[3][1], f.y, a3);
            f2(A[4][0], f.x, a4); f2(A[4][1], f.y, a4);
            f2(A[5][0], f.x, a5); f2(A[5][1], f.y, a5);
            f2(A[6][0], f.x, a6); f2(A[6][1], f.y, a6);
            f2(A[7][0], f.x, a7); f2(A[7][1], f.y, a7);
        }
        float4* dst = (float4*)(g_CTXF + (size_t)n * (H_ * C_));
        #pragma unroll
        for (int j = 0; j < 8; j++) {
            float2 xy = up2(A[j][0]);
            float2 zw = up2(A[j][1]);
            dst[j * 32 + cc] = make_float4(xy.x, xy.y, zw.x, zw.y);
        }
    }
}

// ---------------- kernel C ----------------
__global__ void __launch_bounds__(128) kC(const float* __restrict__ vf,
                                          const float* __restrict__ ipb,
                                          const float* __restrict__ opb,
                                          const float* __restrict__ ln1g, const float* __restrict__ ln1b,
                                          const float* __restrict__ ln2g, const float* __restrict__ ln2b,
                                          const float* __restrict__ ff1b, const float* __restrict__ ff2b,
                                          const float* __restrict__ outb,
                                          const float* __restrict__ ln3g, const float* __restrict__ ln3b,
                                          float* __restrict__ out) {
    __shared__ float bufA[C_ * S_];
    __shared__ float bufC[C_ * S_];
    __shared__ float mean_s[MT], rstd_s[MT];

    int t = threadIdx.x;
    int n0 = blockIdx.x * MT;
    int mg = t & 3, og = t >> 2;
    int mg8 = mg * 8, ch0 = og * 4;

    u64 acc[4][4];
    ZACC(acc);

    // --- ctx: staged ctxfeat chunks (8 x 16 cols) ---
    int rb = (og >> 2) * 16;   // head-row base for this thread's out-channels
    for (int ch = 0; ch < 8; ch++) {
        int c0 = ch * 16;
        __syncthreads();
        {
            int hh = t >> 4, cl = t & 15;
            #pragma unroll
            for (int m4 = 0; m4 < 8; m4++) {
                float a[4];
                #pragma unroll
                for (int j = 0; j < 4; j++) {
                    int n = n0 + 4*m4 + j; if (n >= N_) n = N_ - 1;
                    a[j] = g_CTXF[(size_t)n * (H_*C_) + hh * C_ + c0 + cl];
                }
                *(float4*)&bufC[t * S_ + 4*m4] = make_float4(a[0], a[1], a[2], a[3]);
            }
        }
        __syncthreads();
        #pragma unroll
        for (int cl = 0; cl < 16; cl++) {
            float4 w4 = *(const float4*)&g_wvT[(c0 + cl) * C_ + ch0];
            G2STEP(bufC, rb + cl, w4, acc);
        }
    }
    __syncthreads();
    STORE4(bufC, acc, (const float4*)(ipb + 2 * C_), false);
    __syncthreads();

    // --- attend ---
    ZACC(acc);
    for (int c = 0; c < C_; c++) {
        float4 w4 = *(const float4*)&g_opT[c * C_ + ch0];
        G2STEP(bufC, c, w4, acc);
    }
    __syncthreads();
    STORE4(bufA, acc, (const float4*)opb, false);
    __syncthreads();
    // residual (old layout: thread t owns channel t)
    for (int m = 0; m < MT; m++) {
        int n = n0 + m; if (n >= N_) n = N_ - 1;
        bufA[t * S_ + m] += vf[(size_t)n * C_ + t];
    }
    __syncthreads();
    if (t < MT) {
        float s = 0.f, s2 = 0.f;
        for (int c = 0; c < C_; c++) { float v = bufA[c * S_ + t]; s += v; s2 = fmaf(v, v, s2); }
        float mn = s * (1.f / C_);
        mean_s[t] = mn; rstd_s[t] = rsqrtf(s2 * (1.f / C_) - mn * mn + 1e-5f);
    }
    __syncthreads();
    {
        float g = ln1g[t], b = ln1b[t];
        for (int m = 0; m < MT; m++)
            bufA[t * S_ + m] = (bufA[t * S_ + m] - mean_s[m]) * rstd_s[m] * g + b;
    }
    __syncthreads();

    // --- FF ---
    u64 acc2[4][4];
    ZACC(acc2);
    for (int fc = 0; fc < 2; fc++) {
        ZACC(acc);
        for (int c = 0; c < C_; c++) {
            float4 w4 = *(const float4*)&g_ff1T[c * FF_ + fc * 128 + ch0];
            G2STEP(bufA, c, w4, acc);
        }
        __syncthreads();
        STORE4(bufC, acc, (const float4*)(ff1b + fc * 128), true);
        __syncthreads();
        for (int fl = 0; fl < 128; fl++) {
            float4 w4 = *(const float4*)&g_ff2T[(size_t)(fc * 128 + fl) * C_ + ch0];
            G2STEP(bufC, fl, w4, acc2);
        }
    }
    __syncthreads();
    STORE4(bufC, acc2, (const float4*)ff2b, false);
    __syncthreads();
    // x2 = x1 + ff (old layout)
    for (int m = 0; m < MT; m++)
        bufA[t * S_ + m] += bufC[t * S_ + m];
    __syncthreads();
    if (t < MT) {
        float s = 0.f, s2 = 0.f;
        for (int c = 0; c < C_; c++) { float v = bufA[c * S_ + t]; s += v; s2 = fmaf(v, v, s2); }
        float mn = s * (1.f / C_);
        mean_s[t] = mn; rstd_s[t] = rsqrtf(s2 * (1.f / C_) - mn * mn + 1e-5f);
    }
    __syncthreads();
    {
        float g = ln2g[t], b = ln2b[t];
        for (int m = 0; m < MT; m++)
            bufA[t * S_ + m] = (bufA[t * S_ + m] - mean_s[m]) * rstd_s[m] * g + b;
    }
    __syncthreads();

    // --- out projection ---
    ZACC(acc);
    for (int c = 0; c < C_; c++) {
        float4 w4 = *(const float4*)&g_outT[c * OUT_ + ch0];
        G2STEP(bufA, c, w4, acc);
    }
    __syncthreads();
    STORE4(bufC, acc, (const float4*)outb, false);
    __syncthreads();
    if (t < MT) {
        float s = 0.f, s2 = 0.f;
        for (int c = 0; c < OUT_; c++) { float v = bufC[c * S_ + t]; s += v; s2 = fmaf(v, v, s2); }
        float mn = s * (1.f / OUT_);
        mean_s[t] = mn; rstd_s[t] = rsqrtf(s2 * (1.f / OUT_) - mn * mn + 1e-5f);
    }
    __syncthreads();
    {
        float g = ln3g[t], b = ln3b[t];
        for (int m = 0; m < MT; m++) {
            int n = n0 + m;
            if (n < N_) {
                float v = (bufC[t * S_ + m] - mean_s[m]) * rstd_s[m] * g + b;
                out[(size_t)n * OUT_ + t] = fmaxf(v, 0.f);
            }
        }
    }
}

// ---------------- launch ----------------
extern "C" void kernel_launch(void* const* d_in, const int* in_sizes, int n_in,
                              void* d_out, int out_size) {
    const float* vf     = (const float*)d_in[0];
    const float* coords = (const float*)d_in[1];
    const int*   kidx   = (const int*)  d_in[2];
    const void*  kmask  =               d_in[3];
    const float* ipw    = (const float*)d_in[4];
    const float* ipb    = (const float*)d_in[5];
    const float* opw    = (const float*)d_in[6];
    const float* opb    = (const float*)d_in[7];
    const float* kpw    = (const float*)d_in[8];
    const float* kpb    = (const float*)d_in[9];
    const float* ln1g   = (const float*)d_in[10];
    const float* ln1b   = (const float*)d_in[11];
    const float* ln2g   = (const float*)d_in[12];
    const float* ln2b   = (const float*)d_in[13];
    const float* ff1w   = (const float*)d_in[14];
    const float* ff1b   = (const float*)d_in[15];
    const float* ff2w   = (const float*)d_in[16];
    const float* ff2b   = (const float*)d_in[17];
    const float* outw   = (const float*)d_in[18];
    const float* outb   = (const float*)d_in[19];
    const float* ln3g   = (const float*)d_in[20];
    const float* ln3b   = (const float*)d_in[21];

    kDetect<<<1, 256>>>((const int*)kmask);
    kPrep<<<(131072 + 255) / 256, 256>>>(ipw, opw, ff1w, ff2w, outw);
    kA<<<NBLK, 128>>>(vf, ipw, ipb);
    kB<<<N_, 128>>>(vf, coords, kidx, kmask, kpw, kpb);
    kC<<<NBLK, 128>>>(vf, ipb, opb, ln1g, ln1b, ln2g, ln2b,
                      ff1b, ff2b, outb, ln3g, ln3b, (float*)d_out);
}